// round 6
// baseline (speedup 1.0000x reference)
#include <cuda_runtime.h>
#include <cuda_fp16.h>
#include <math.h>
#include <stdint.h>

#define BATCH 8
#define SEQ   2048
#define DIM   768
#define MTOT  (BATCH*SEQ)

// ---------------- static device scratch ----------------
__device__ __half g_xh [(size_t)MTOT*DIM];
__device__ __half g_Wqh[DIM*DIM], g_Wql[DIM*DIM];
__device__ __half g_Wkh[DIM*DIM], g_Wkl[DIM*DIM];
__device__ __half g_Wvh[DIM*DIM], g_Wvl[DIM*DIM];
__device__ __half g_Qh [(size_t)MTOT*DIM];
__device__ __half g_Kh [(size_t)MTOT*DIM];
__device__ __half g_Vth[(size_t)DIM*MTOT];
__device__ float  g_P  [(size_t)BATCH*SEQ*SEQ];
__device__ __half g_Ph [(size_t)BATCH*SEQ*SEQ];

// ---------------- tiling ----------------
#define BM 128
#define BN 128
#define BK 64
#define ROWB 144                       // 64 fp16 (128B) + 16B pad
#define TILE_SMEM (128*ROWB)           // 18432 B
// TwoTerm: 3 tiles/stage x 3 stages = 165888 B ; OneTerm: 2 tiles x 4 stages = 147456 B

// ---------------- PTX helpers ----------------
__device__ __forceinline__ uint32_t smem_u32(const void* p) {
    uint32_t a;
    asm("{ .reg .u64 t; cvta.to.shared.u64 t, %1; cvt.u32.u64 %0, t; }" : "=r"(a) : "l"(p));
    return a;
}
__device__ __forceinline__ void cp_async16(uint32_t saddr, const void* gaddr) {
    asm volatile("cp.async.cg.shared.global [%0], [%1], 16;" :: "r"(saddr), "l"(gaddr));
}
__device__ __forceinline__ void cp_commit() {
    asm volatile("cp.async.commit_group;" ::: "memory");
}
template<int N> __device__ __forceinline__ void cp_wait() {
    asm volatile("cp.async.wait_group %0;" :: "n"(N) : "memory");
}
__device__ __forceinline__ void ldsm4(uint32_t* r, uint32_t addr) {
    asm volatile("ldmatrix.sync.aligned.m8n8.x4.shared.b16 {%0,%1,%2,%3}, [%4];"
                 : "=r"(r[0]), "=r"(r[1]), "=r"(r[2]), "=r"(r[3]) : "r"(addr));
}
__device__ __forceinline__ void mma16816(float* c, const uint32_t* a, const uint32_t* b) {
    asm volatile(
        "mma.sync.aligned.m16n8k16.row.col.f32.f16.f16.f32 "
        "{%0,%1,%2,%3}, {%4,%5,%6,%7}, {%8,%9}, {%0,%1,%2,%3};"
        : "+f"(c[0]), "+f"(c[1]), "+f"(c[2]), "+f"(c[3])
        : "r"(a[0]), "r"(a[1]), "r"(a[2]), "r"(a[3]), "r"(b[0]), "r"(b[1]));
}

// ---------------- GEMM: C[M,N] = scale * (A@B^T [+ term2]), fp16 NT ----------------
// TwoTerm: adds Lo@B^T (LoSideA) or A@Lo^T.
// mode: 0 -> fp32 out (*scale), 2 -> fp16 out
// QKF: gridDim.z=2 selects (Wq,Wql -> Qh) / (Wk,Wkl -> Kh); B/Lo/C args ignored.
template<bool TwoTerm, bool LoSideA, bool QKF>
__global__ void __launch_bounds__(256, 1) gemm_tc(
    const __half* __restrict__ A, const __half* __restrict__ Bp,
    const __half* __restrict__ Lop,
    float* __restrict__ Cf, __half* __restrict__ Chp,
    int K, int lda, int ldb, int ldc,
    long sA, long sB, long sC, float scale, int mode)
{
    constexpr int TILES  = TwoTerm ? 3 : 2;
    constexpr int STAGES = TwoTerm ? 3 : 4;
    constexpr int STAGE_SMEM = TILES * TILE_SMEM;
    constexpr int NCHUNK = TILES * 4;          // 16B chunks per thread per stage

    extern __shared__ char smem[];
    const uint32_t sb = smem_u32(smem);
    const int tid  = threadIdx.x;
    const int lane = tid & 31;
    const int wid  = tid >> 5;
    const int wm   = wid & 1;
    const int wn   = wid >> 1;
    const long z = blockIdx.z;

    const __half* AB = A + (QKF ? 0 : z * sA);
    const __half* BB;
    const __half* LoB;
    __half* Ch;
    if (QKF) {
        BB  = (z == 0) ? g_Wqh : g_Wkh;
        LoB = (z == 0) ? g_Wql : g_Wkl;
        Ch  = (z == 0) ? g_Qh  : g_Kh;
    } else {
        BB  = Bp + z * sB;
        LoB = TwoTerm ? (Lop + z * (LoSideA ? sA : sB)) : nullptr;
        Ch  = Chp ? Chp + z * sC : nullptr;
    }

    const int rowBase = blockIdx.y * BM;
    const int colBase = blockIdx.x * BN;

    // ---- cp.async source mapping ----
    const __half* gsrc[NCHUNK];
    uint32_t soff[NCHUNK];
#pragma unroll
    for (int i = 0; i < NCHUNK; i++) {
        int idx  = tid + i * 256;
        int tile = idx >> 10;              // 0:A 1:B 2:Lo
        int w    = idx & 1023;
        int row  = w >> 3;
        int ch   = w & 7;
        const __half* s;
        int rs, ld;
        if (tile == 0)      { s = AB;  rs = rowBase; ld = lda; }
        else if (tile == 1) { s = BB;  rs = colBase; ld = ldb; }
        else {
            s  = LoB;
            rs = LoSideA ? rowBase : colBase;
            ld = LoSideA ? lda : ldb;
        }
        gsrc[i] = s + (long)(rs + row) * ld + ch * 8;
        soff[i] = tile * TILE_SMEM + row * ROWB + ch * 16;
    }

    // ---- ldmatrix lane offsets ----
    const int j = lane >> 3, r = lane & 7;
    const uint32_t aOff = (uint32_t)(wm * 64 + (j & 1) * 8 + r) * ROWB + ((j >> 1) * 8) * 2;
    const uint32_t bOff = (uint32_t)(wn * 32 + (j >> 1) * 8 + r) * ROWB + ((j & 1) * 8) * 2;

    const int kTiles = K / BK;

    // ---- prologue ----
#pragma unroll
    for (int s = 0; s < STAGES - 1; s++) {
        int k0 = s * BK;
#pragma unroll
        for (int i = 0; i < NCHUNK; i++)
            cp_async16(sb + s * STAGE_SMEM + soff[i], gsrc[i] + k0);
        cp_commit();
    }

    float acc[4][4][4];
#pragma unroll
    for (int a = 0; a < 4; a++)
#pragma unroll
        for (int b = 0; b < 4; b++)
#pragma unroll
            for (int q = 0; q < 4; q++) acc[a][b][q] = 0.f;

    uint32_t ah[2][4][4], bh[2][4][2], lo[2][4][4];

    for (int kt = 0; kt < kTiles; kt++) {
        cp_wait<STAGES - 2>();
        __syncthreads();

        {
            int ft = kt + STAGES - 1;
            if (ft < kTiles) {
                uint32_t sbase = sb + (ft % STAGES) * STAGE_SMEM;
                int k0 = ft * BK;
#pragma unroll
                for (int i = 0; i < NCHUNK; i++)
                    cp_async16(sbase + soff[i], gsrc[i] + k0);
            }
            cp_commit();
        }

        const uint32_t stage = sb + (kt % STAGES) * STAGE_SMEM;

#define LOAD_FRAGS(ks, bi)                                                        \
        do {                                                                      \
            const uint32_t kb = (ks) * 32;                                        \
            _Pragma("unroll")                                                     \
            for (int mt = 0; mt < 4; mt++)                                        \
                ldsm4(ah[bi][mt], stage + 0 * TILE_SMEM + aOff + mt * 16 * ROWB + kb); \
            _Pragma("unroll")                                                     \
            for (int p = 0; p < 2; p++) {                                         \
                uint32_t t[4];                                                    \
                ldsm4(t, stage + 1 * TILE_SMEM + bOff + p * 16 * ROWB + kb);      \
                bh[bi][2 * p][0] = t[0]; bh[bi][2 * p][1] = t[1];                 \
                bh[bi][2 * p + 1][0] = t[2]; bh[bi][2 * p + 1][1] = t[3];         \
            }                                                                     \
            if (TwoTerm) {                                                        \
                if (LoSideA) {                                                    \
                    _Pragma("unroll")                                             \
                    for (int mt = 0; mt < 4; mt++)                                \
                        ldsm4(lo[bi][mt], stage + 2 * TILE_SMEM + aOff + mt * 16 * ROWB + kb); \
                } else {                                                          \
                    _Pragma("unroll")                                             \
                    for (int p = 0; p < 2; p++) {                                 \
                        uint32_t t[4];                                            \
                        ldsm4(t, stage + 2 * TILE_SMEM + bOff + p * 16 * ROWB + kb); \
                        lo[bi][2 * p][0] = t[0]; lo[bi][2 * p][1] = t[1];         \
                        lo[bi][2 * p + 1][0] = t[2]; lo[bi][2 * p + 1][1] = t[3]; \
                    }                                                             \
                }                                                                 \
            }                                                                     \
        } while (0)

        LOAD_FRAGS(0, 0);
#pragma unroll
        for (int ks = 0; ks < 4; ks++) {
            const int cur = ks & 1;
            if (ks < 3) LOAD_FRAGS(ks + 1, (ks + 1) & 1);
#pragma unroll
            for (int mt = 0; mt < 4; mt++)
#pragma unroll
                for (int nt = 0; nt < 4; nt++)
                    mma16816(acc[mt][nt], ah[cur][mt], bh[cur][nt]);
            if (TwoTerm) {
                if (LoSideA) {
#pragma unroll
                    for (int mt = 0; mt < 4; mt++)
#pragma unroll
                        for (int nt = 0; nt < 4; nt++)
                            mma16816(acc[mt][nt], lo[cur][mt], bh[cur][nt]);
                } else {
#pragma unroll
                    for (int mt = 0; mt < 4; mt++)
#pragma unroll
                        for (int nt = 0; nt < 4; nt++)
                            mma16816(acc[mt][nt], ah[cur][mt], lo[cur][nt]);
                }
            }
        }
#undef LOAD_FRAGS
    }

    // ---- epilogue ----
    const int mRow0 = rowBase + wm * 64 + (lane >> 2);
    const int nCol0 = colBase + wn * 32 + 2 * (lane & 3);

    if (!QKF && mode == 0) {
        float* C = Cf + z * sC;
#pragma unroll
        for (int mt = 0; mt < 4; mt++) {
#pragma unroll
            for (int nt = 0; nt < 4; nt++) {
                float* c = acc[mt][nt];
                long r0 = mRow0 + mt * 16;
                int  cc = nCol0 + nt * 8;
                *(float2*)(C + r0 * ldc + cc)       = make_float2(c[0] * scale, c[1] * scale);
                *(float2*)(C + (r0 + 8) * ldc + cc) = make_float2(c[2] * scale, c[3] * scale);
            }
        }
    } else {
#pragma unroll
        for (int mt = 0; mt < 4; mt++) {
#pragma unroll
            for (int nt = 0; nt < 4; nt++) {
                float* c = acc[mt][nt];
                long r0 = mRow0 + mt * 16;
                int  cc = nCol0 + nt * 8;
#pragma unroll
                for (int h = 0; h < 2; h++) {
                    long rr = r0 + 8 * h;
                    __half2 hp;
                    hp.x = __float2half(c[2 * h]);
                    hp.y = __float2half(c[2 * h + 1]);
                    *(__half2*)(Ch + rr * ldc + cc) = hp;
                }
            }
        }
    }
}

// ---------------- conversions ----------------
__global__ void __launch_bounds__(256) to_h(const float* __restrict__ s,
                                            __half* __restrict__ h, int n)
{
    for (int i = blockIdx.x * 256 + threadIdx.x; i < n; i += gridDim.x * 256)
        h[i] = __float2half(s[i]);
}
__global__ void __launch_bounds__(256) to_hilo(const float* __restrict__ s,
                                               __half* __restrict__ h,
                                               __half* __restrict__ l, int n)
{
    for (int i = blockIdx.x * 256 + threadIdx.x; i < n; i += gridDim.x * 256) {
        float v = s[i];
        __half hi = __float2half(v);
        h[i] = hi;
        l[i] = __float2half(v - __half2float(hi));
    }
}

// ---------------- softmax ----------------
__global__ void __launch_bounds__(256) softmax_rows(const float* __restrict__ P,
                                                    __half* __restrict__ Ph)
{
    __shared__ float red[256];
    const float* p = P + (long)blockIdx.x * SEQ;
    __half* ph = Ph + (long)blockIdx.x * SEQ;
    const int t = threadIdx.x;

    float v[8];
    float m = -1e30f;
#pragma unroll
    for (int i = 0; i < 8; i++) { v[i] = p[t + i * 256]; m = fmaxf(m, v[i]); }
    red[t] = m; __syncthreads();
    for (int s = 128; s > 0; s >>= 1) {
        if (t < s) red[t] = fmaxf(red[t], red[t + s]);
        __syncthreads();
    }
    m = red[0]; __syncthreads();

    float sum = 0.f;
#pragma unroll
    for (int i = 0; i < 8; i++) { v[i] = __expf(v[i] - m); sum += v[i]; }
    red[t] = sum; __syncthreads();
    for (int s = 128; s > 0; s >>= 1) {
        if (t < s) red[t] += red[t + s];
        __syncthreads();
    }
    float inv = 1.0f / red[0];
#pragma unroll
    for (int i = 0; i < 8; i++)
        ph[t + i * 256] = __float2half(v[i] * inv);
}

// ---------------- host launcher ----------------
extern "C" void kernel_launch(void* const* d_in, const int* in_sizes, int n_in,
                              void* d_out, int out_size)
{
    const float* x  = (const float*)d_in[0];
    const float* Wq = (const float*)d_in[1];
    const float* Wk = (const float*)d_in[2];
    const float* Wv = (const float*)d_in[3];
    float* out = (float*)d_out;

    const int SMEM_2T = 3 * 3 * TILE_SMEM;   // 165888
    const int SMEM_1T = 4 * 2 * TILE_SMEM;   // 147456
    cudaFuncSetAttribute((const void*)gemm_tc<true,  false, true>,  cudaFuncAttributeMaxDynamicSharedMemorySize, SMEM_2T);
    cudaFuncSetAttribute((const void*)gemm_tc<true,  true,  false>, cudaFuncAttributeMaxDynamicSharedMemorySize, SMEM_2T);
    cudaFuncSetAttribute((const void*)gemm_tc<false, false, false>, cudaFuncAttributeMaxDynamicSharedMemorySize, SMEM_1T);

    __half *xh,*Wqh,*Wql,*Wkh,*Wkl,*Wvh,*Wvl,*Qh,*Kh,*Vth,*Ph;
    float *P;
    cudaGetSymbolAddress((void**)&xh, g_xh);
    cudaGetSymbolAddress((void**)&Wqh, g_Wqh); cudaGetSymbolAddress((void**)&Wql, g_Wql);
    cudaGetSymbolAddress((void**)&Wkh, g_Wkh); cudaGetSymbolAddress((void**)&Wkl, g_Wkl);
    cudaGetSymbolAddress((void**)&Wvh, g_Wvh); cudaGetSymbolAddress((void**)&Wvl, g_Wvl);
    cudaGetSymbolAddress((void**)&Qh, g_Qh);
    cudaGetSymbolAddress((void**)&Kh, g_Kh);
    cudaGetSymbolAddress((void**)&Vth, g_Vth);
    cudaGetSymbolAddress((void**)&P, g_P);
    cudaGetSymbolAddress((void**)&Ph, g_Ph);

    const float scale = 1.0f / sqrtf((float)DIM);

    // 1) conversions
    to_h   <<<4096, 256>>>(x,  xh,  MTOT * DIM);
    to_hilo<<<2304, 256>>>(Wq, Wqh, Wql, DIM * DIM);
    to_hilo<<<2304, 256>>>(Wk, Wkh, Wkl, DIM * DIM);
    to_hilo<<<2304, 256>>>(Wv, Wvh, Wvl, DIM * DIM);

    // 2) fused Q&K projections: z -> (Wq->Qh) / (Wk->Kh), 2-term (W hi+lo), fp16 out
    {
        dim3 g(DIM / BN, MTOT / BM, 2);
        gemm_tc<true, false, true><<<g, 256, SMEM_2T>>>(xh, nullptr, nullptr,
                                                        nullptr, nullptr,
                                                        DIM, DIM, DIM, DIM, 0, 0, 0, 1.0f, 2);
    }
    // 3) Vt = (Wvh+Wvl)@x^T -> fp16 [DIM, MTOT]
    {
        dim3 g(MTOT / BN, DIM / BM, 1);
        gemm_tc<true, true, false><<<g, 256, SMEM_2T>>>(Wvh, xh, Wvl, nullptr, Vth,
                                                        DIM, DIM, DIM, MTOT, 0, 0, 0, 1.0f, 2);
    }
    // 4) scores = scale * Qh@Kh^T -> fp32 (single term)
    {
        dim3 g(SEQ / BN, SEQ / BM, BATCH);
        gemm_tc<false, false, false><<<g, 256, SMEM_1T>>>(Qh, Kh, nullptr, P, nullptr,
                                                          DIM, DIM, DIM, SEQ,
                                                          (long)SEQ * DIM, (long)SEQ * DIM,
                                                          (long)SEQ * SEQ, scale, 0);
    }
    // 5) softmax -> fp16
    softmax_rows<<<BATCH * SEQ, 256>>>(P, Ph);

    // 6) H = Ph@Vth^T -> fp32 out (single term)
    {
        dim3 g(DIM / BN, SEQ / BM, BATCH);
        gemm_tc<false, false, false><<<g, 256, SMEM_1T>>>(Ph, Vth, nullptr, out, nullptr,
                                                          SEQ, SEQ, MTOT, DIM,
                                                          (long)SEQ * SEQ, (long)SEQ,
                                                          (long)SEQ * DIM, 1.0f, 0);
    }
}

// round 7
// speedup vs baseline: 1.6091x; 1.6091x over previous
#include <cuda_runtime.h>
#include <cuda_fp16.h>
#include <math.h>
#include <stdint.h>

#define BATCH 8
#define SEQ   2048
#define DIM   768
#define MTOT  (BATCH*SEQ)

// ---------------- static device scratch ----------------
__device__ __half g_xh [(size_t)MTOT*DIM];
__device__ __half g_Wqh[DIM*DIM], g_Wql[DIM*DIM];
__device__ __half g_Wkh[DIM*DIM], g_Wkl[DIM*DIM];
__device__ __half g_Wvh[DIM*DIM], g_Wvl[DIM*DIM];
__device__ __half g_Qh [(size_t)MTOT*DIM];
__device__ __half g_Kh [(size_t)MTOT*DIM];
__device__ __half g_Vth[(size_t)DIM*MTOT];
__device__ float  g_P  [(size_t)BATCH*SEQ*SEQ];
__device__ __half g_Ph [(size_t)BATCH*SEQ*SEQ];

// ---------------- tiling ----------------
#define BM 128
#define BN 128
#define BK 64
#define ROWB 144                       // 64 fp16 (128B) + 16B pad
#define TILE_SMEM (128*ROWB)           // 18432 B
#define SMEM_2T (3*3*TILE_SMEM)        // 2-term: 3 tiles x 3 stages = 165888 B

// wide 1-term kernel
#define WBN 256
#define WB_TILE (256*ROWB)             // 36864 B
#define WSTAGE (TILE_SMEM + WB_TILE)   // 55296 B
#define SMEM_W (3*WSTAGE)              // 165888 B

// ---------------- PTX helpers ----------------
__device__ __forceinline__ uint32_t smem_u32(const void* p) {
    uint32_t a;
    asm("{ .reg .u64 t; cvta.to.shared.u64 t, %1; cvt.u32.u64 %0, t; }" : "=r"(a) : "l"(p));
    return a;
}
__device__ __forceinline__ void cp_async16(uint32_t saddr, const void* gaddr) {
    asm volatile("cp.async.cg.shared.global [%0], [%1], 16;" :: "r"(saddr), "l"(gaddr));
}
__device__ __forceinline__ void cp_commit() {
    asm volatile("cp.async.commit_group;" ::: "memory");
}
template<int N> __device__ __forceinline__ void cp_wait() {
    asm volatile("cp.async.wait_group %0;" :: "n"(N) : "memory");
}
__device__ __forceinline__ void ldsm4(uint32_t* r, uint32_t addr) {
    asm volatile("ldmatrix.sync.aligned.m8n8.x4.shared.b16 {%0,%1,%2,%3}, [%4];"
                 : "=r"(r[0]), "=r"(r[1]), "=r"(r[2]), "=r"(r[3]) : "r"(addr));
}
__device__ __forceinline__ void mma16816(float* c, const uint32_t* a, const uint32_t* b) {
    asm volatile(
        "mma.sync.aligned.m16n8k16.row.col.f32.f16.f16.f32 "
        "{%0,%1,%2,%3}, {%4,%5,%6,%7}, {%8,%9}, {%0,%1,%2,%3};"
        : "+f"(c[0]), "+f"(c[1]), "+f"(c[2]), "+f"(c[3])
        : "r"(a[0]), "r"(a[1]), "r"(a[2]), "r"(a[3]), "r"(b[0]), "r"(b[1]));
}

// ============ 2-term GEMM (R5-proven): C = A@B^T + (Lo@B^T | A@Lo^T), fp16 out ============
// QKF: gridDim.z selects (Wq,Wql->Qh)/(Wk,Wkl->Kh); B/Lo/C args ignored.
template<bool LoSideA, bool QKF>
__global__ void __launch_bounds__(256, 1) gemm_2t(
    const __half* __restrict__ A, const __half* __restrict__ Bp,
    const __half* __restrict__ Lop, __half* __restrict__ Chp,
    int K, int lda, int ldb, int ldc, long sC)
{
    constexpr int STAGES = 3;
    constexpr int STAGE_SMEM = 3 * TILE_SMEM;

    extern __shared__ char smem[];
    const uint32_t sb = smem_u32(smem);
    const int tid  = threadIdx.x;
    const int lane = tid & 31;
    const int wid  = tid >> 5;
    const int wm   = wid & 1;
    const int wn   = wid >> 1;
    const long z = blockIdx.z;

    const __half* AB = A;
    const __half* BB;
    const __half* LoB;
    __half* Ch;
    if (QKF) {
        BB  = (z == 0) ? g_Wqh : g_Wkh;
        LoB = (z == 0) ? g_Wql : g_Wkl;
        Ch  = (z == 0) ? g_Qh  : g_Kh;
    } else {
        BB  = Bp;
        LoB = Lop;
        Ch  = Chp + z * sC;
    }

    const int rowBase = blockIdx.y * BM;
    const int colBase = blockIdx.x * BN;

    const __half* gsrc[12];
    uint32_t soff[12];
#pragma unroll
    for (int i = 0; i < 12; i++) {
        int idx  = tid + i * 256;
        int tile = idx >> 10;
        int w    = idx & 1023;
        int row  = w >> 3;
        int ch   = w & 7;
        const __half* s;
        int rs, ld;
        if (tile == 0)      { s = AB;  rs = rowBase; ld = lda; }
        else if (tile == 1) { s = BB;  rs = colBase; ld = ldb; }
        else {
            s  = LoB;
            rs = LoSideA ? rowBase : colBase;
            ld = LoSideA ? lda : ldb;
        }
        gsrc[i] = s + (long)(rs + row) * ld + ch * 8;
        soff[i] = tile * TILE_SMEM + row * ROWB + ch * 16;
    }

    const int j = lane >> 3, r = lane & 7;
    const uint32_t aOff = (uint32_t)(wm * 64 + (j & 1) * 8 + r) * ROWB + ((j >> 1) * 8) * 2;
    const uint32_t bOff = (uint32_t)(wn * 32 + (j >> 1) * 8 + r) * ROWB + ((j & 1) * 8) * 2;

    const int kTiles = K / BK;

#pragma unroll
    for (int s = 0; s < STAGES - 1; s++) {
        int k0 = s * BK;
#pragma unroll
        for (int i = 0; i < 12; i++)
            cp_async16(sb + s * STAGE_SMEM + soff[i], gsrc[i] + k0);
        cp_commit();
    }

    float acc[4][4][4];
#pragma unroll
    for (int a = 0; a < 4; a++)
#pragma unroll
        for (int b = 0; b < 4; b++)
#pragma unroll
            for (int q = 0; q < 4; q++) acc[a][b][q] = 0.f;

    uint32_t ah[2][4][4], bh[2][4][2], lo[2][4][4];

    for (int kt = 0; kt < kTiles; kt++) {
        cp_wait<STAGES - 2>();
        __syncthreads();

        {
            int ft = kt + STAGES - 1;
            if (ft < kTiles) {
                uint32_t sbase = sb + (ft % STAGES) * STAGE_SMEM;
                int k0 = ft * BK;
#pragma unroll
                for (int i = 0; i < 12; i++)
                    cp_async16(sbase + soff[i], gsrc[i] + k0);
            }
            cp_commit();
        }

        const uint32_t stage = sb + (kt % STAGES) * STAGE_SMEM;

#define LOAD_FRAGS(ks, bi)                                                        \
        do {                                                                      \
            const uint32_t kb = (ks) * 32;                                        \
            _Pragma("unroll")                                                     \
            for (int mt = 0; mt < 4; mt++)                                        \
                ldsm4(ah[bi][mt], stage + 0 * TILE_SMEM + aOff + mt * 16 * ROWB + kb); \
            _Pragma("unroll")                                                     \
            for (int p = 0; p < 2; p++) {                                         \
                uint32_t t[4];                                                    \
                ldsm4(t, stage + 1 * TILE_SMEM + bOff + p * 16 * ROWB + kb);      \
                bh[bi][2 * p][0] = t[0]; bh[bi][2 * p][1] = t[1];                 \
                bh[bi][2 * p + 1][0] = t[2]; bh[bi][2 * p + 1][1] = t[3];         \
            }                                                                     \
            if (LoSideA) {                                                        \
                _Pragma("unroll")                                                 \
                for (int mt = 0; mt < 4; mt++)                                    \
                    ldsm4(lo[bi][mt], stage + 2 * TILE_SMEM + aOff + mt * 16 * ROWB + kb); \
            } else {                                                              \
                _Pragma("unroll")                                                 \
                for (int p = 0; p < 2; p++) {                                     \
                    uint32_t t[4];                                                \
                    ldsm4(t, stage + 2 * TILE_SMEM + bOff + p * 16 * ROWB + kb);  \
                    lo[bi][2 * p][0] = t[0]; lo[bi][2 * p][1] = t[1];             \
                    lo[bi][2 * p + 1][0] = t[2]; lo[bi][2 * p + 1][1] = t[3];     \
                }                                                                 \
            }                                                                     \
        } while (0)

        LOAD_FRAGS(0, 0);
#pragma unroll
        for (int ks = 0; ks < 4; ks++) {
            const int cur = ks & 1;
            if (ks < 3) LOAD_FRAGS(ks + 1, (ks + 1) & 1);
#pragma unroll
            for (int mt = 0; mt < 4; mt++)
#pragma unroll
                for (int nt = 0; nt < 4; nt++)
                    mma16816(acc[mt][nt], ah[cur][mt], bh[cur][nt]);
            if (LoSideA) {
#pragma unroll
                for (int mt = 0; mt < 4; mt++)
#pragma unroll
                    for (int nt = 0; nt < 4; nt++)
                        mma16816(acc[mt][nt], lo[cur][mt], bh[cur][nt]);
            } else {
#pragma unroll
                for (int mt = 0; mt < 4; mt++)
#pragma unroll
                    for (int nt = 0; nt < 4; nt++)
                        mma16816(acc[mt][nt], ah[cur][mt], lo[cur][nt]);
            }
        }
#undef LOAD_FRAGS
    }

    const int mRow0 = rowBase + wm * 64 + (lane >> 2);
    const int nCol0 = colBase + wn * 32 + 2 * (lane & 3);
#pragma unroll
    for (int mt = 0; mt < 4; mt++) {
#pragma unroll
        for (int nt = 0; nt < 4; nt++) {
            float* c = acc[mt][nt];
            long r0 = mRow0 + mt * 16;
            int  cc = nCol0 + nt * 8;
#pragma unroll
            for (int h = 0; h < 2; h++) {
                long rr = r0 + 8 * h;
                __half2 hp;
                hp.x = __float2half(c[2 * h]);
                hp.y = __float2half(c[2 * h + 1]);
                *(__half2*)(Ch + rr * ldc + cc) = hp;
            }
        }
    }
}

// ============ wide 1-term GEMM: C[M,N] = scale * A@B^T, BN=256, fp32 out ============
__global__ void __launch_bounds__(256, 1) gemm_w1(
    const __half* __restrict__ A, const __half* __restrict__ Bp,
    float* __restrict__ Cf,
    int K, int lda, int ldb, int ldc,
    long sA, long sB, long sC, float scale)
{
    constexpr int STAGES = 3;

    extern __shared__ char smem[];
    const uint32_t sb = smem_u32(smem);
    const int tid  = threadIdx.x;
    const int lane = tid & 31;
    const int wid  = tid >> 5;
    const int wm   = wid & 1;        // 2 x 64 rows
    const int wn   = wid >> 1;       // 4 x 64 cols
    const long z = blockIdx.z;

    const __half* AB = A  + z * sA;
    const __half* BB = Bp + z * sB;

    const int rowBase = blockIdx.y * BM;
    const int colBase = blockIdx.x * WBN;

    // cp.async: 12 chunks/thread (A: 1024 chunks, B: 2048 chunks)
    const __half* gsrc[12];
    uint32_t soff[12];
#pragma unroll
    for (int i = 0; i < 12; i++) {
        int idx = tid + i * 256;           // 0..3071
        if (idx < 1024) {
            int row = idx >> 3, ch = idx & 7;
            gsrc[i] = AB + (long)(rowBase + row) * lda + ch * 8;
            soff[i] = row * ROWB + ch * 16;
        } else {
            int w = idx - 1024;
            int row = w >> 3, ch = w & 7;
            gsrc[i] = BB + (long)(colBase + row) * ldb + ch * 8;
            soff[i] = TILE_SMEM + row * ROWB + ch * 16;
        }
    }

    const int j = lane >> 3, r = lane & 7;
    const uint32_t aOff = (uint32_t)(wm * 64 + (j & 1) * 8 + r) * ROWB + ((j >> 1) * 8) * 2;
    const uint32_t bOff = (uint32_t)(wn * 64 + (j >> 1) * 8 + r) * ROWB + ((j & 1) * 8) * 2;

    const int kTiles = K / BK;

#pragma unroll
    for (int s = 0; s < STAGES - 1; s++) {
        int k0 = s * BK;
#pragma unroll
        for (int i = 0; i < 12; i++)
            cp_async16(sb + s * WSTAGE + soff[i], gsrc[i] + k0);
        cp_commit();
    }

    float acc[4][8][4];
#pragma unroll
    for (int a = 0; a < 4; a++)
#pragma unroll
        for (int b = 0; b < 8; b++)
#pragma unroll
            for (int q = 0; q < 4; q++) acc[a][b][q] = 0.f;

    uint32_t ah[2][4][4], bh[2][8][2];

    for (int kt = 0; kt < kTiles; kt++) {
        cp_wait<STAGES - 2>();
        __syncthreads();

        {
            int ft = kt + STAGES - 1;
            if (ft < kTiles) {
                uint32_t sbase = sb + (ft % STAGES) * WSTAGE;
                int k0 = ft * BK;
#pragma unroll
                for (int i = 0; i < 12; i++)
                    cp_async16(sbase + soff[i], gsrc[i] + k0);
            }
            cp_commit();
        }

        const uint32_t stage = sb + (kt % STAGES) * WSTAGE;

#define WLOAD(ks, bi)                                                             \
        do {                                                                      \
            const uint32_t kb = (ks) * 32;                                        \
            _Pragma("unroll")                                                     \
            for (int mt = 0; mt < 4; mt++)                                        \
                ldsm4(ah[bi][mt], stage + aOff + mt * 16 * ROWB + kb);            \
            _Pragma("unroll")                                                     \
            for (int p = 0; p < 4; p++) {                                         \
                uint32_t t[4];                                                    \
                ldsm4(t, stage + TILE_SMEM + bOff + p * 16 * ROWB + kb);          \
                bh[bi][2 * p][0] = t[0]; bh[bi][2 * p][1] = t[1];                 \
                bh[bi][2 * p + 1][0] = t[2]; bh[bi][2 * p + 1][1] = t[3];         \
            }                                                                     \
        } while (0)

        WLOAD(0, 0);
#pragma unroll
        for (int ks = 0; ks < 4; ks++) {
            const int cur = ks & 1;
            if (ks < 3) WLOAD(ks + 1, (ks + 1) & 1);
#pragma unroll
            for (int mt = 0; mt < 4; mt++)
#pragma unroll
                for (int nt = 0; nt < 8; nt++)
                    mma16816(acc[mt][nt], ah[cur][mt], bh[cur][nt]);
        }
#undef WLOAD
    }

    float* C = Cf + z * sC;
    const int mRow0 = rowBase + wm * 64 + (lane >> 2);
    const int nCol0 = colBase + wn * 64 + 2 * (lane & 3);
#pragma unroll
    for (int mt = 0; mt < 4; mt++) {
#pragma unroll
        for (int nt = 0; nt < 8; nt++) {
            float* c = acc[mt][nt];
            long r0 = mRow0 + mt * 16;
            int  cc = nCol0 + nt * 8;
            *(float2*)(C + r0 * ldc + cc)       = make_float2(c[0] * scale, c[1] * scale);
            *(float2*)(C + (r0 + 8) * ldc + cc) = make_float2(c[2] * scale, c[3] * scale);
        }
    }
}

// ---------------- conversions ----------------
__global__ void __launch_bounds__(256) to_h(const float* __restrict__ s,
                                            __half* __restrict__ h, int n)
{
    for (int i = blockIdx.x * 256 + threadIdx.x; i < n; i += gridDim.x * 256)
        h[i] = __float2half(s[i]);
}
__global__ void __launch_bounds__(256) to_hilo(const float* __restrict__ s,
                                               __half* __restrict__ h,
                                               __half* __restrict__ l, int n)
{
    for (int i = blockIdx.x * 256 + threadIdx.x; i < n; i += gridDim.x * 256) {
        float v = s[i];
        __half hi = __float2half(v);
        h[i] = hi;
        l[i] = __float2half(v - __half2float(hi));
    }
}

// ---------------- softmax ----------------
__global__ void __launch_bounds__(256) softmax_rows(const float* __restrict__ P,
                                                    __half* __restrict__ Ph)
{
    __shared__ float red[256];
    const float* p = P + (long)blockIdx.x * SEQ;
    __half* ph = Ph + (long)blockIdx.x * SEQ;
    const int t = threadIdx.x;

    float v[8];
    float m = -1e30f;
#pragma unroll
    for (int i = 0; i < 8; i++) { v[i] = p[t + i * 256]; m = fmaxf(m, v[i]); }
    red[t] = m; __syncthreads();
    for (int s = 128; s > 0; s >>= 1) {
        if (t < s) red[t] = fmaxf(red[t], red[t + s]);
        __syncthreads();
    }
    m = red[0]; __syncthreads();

    float sum = 0.f;
#pragma unroll
    for (int i = 0; i < 8; i++) { v[i] = __expf(v[i] - m); sum += v[i]; }
    red[t] = sum; __syncthreads();
    for (int s = 128; s > 0; s >>= 1) {
        if (t < s) red[t] += red[t + s];
        __syncthreads();
    }
    float inv = 1.0f / red[0];
#pragma unroll
    for (int i = 0; i < 8; i++)
        ph[t + i * 256] = __float2half(v[i] * inv);
}

// ---------------- host launcher ----------------
extern "C" void kernel_launch(void* const* d_in, const int* in_sizes, int n_in,
                              void* d_out, int out_size)
{
    const float* x  = (const float*)d_in[0];
    const float* Wq = (const float*)d_in[1];
    const float* Wk = (const float*)d_in[2];
    const float* Wv = (const float*)d_in[3];
    float* out = (float*)d_out;

    cudaFuncSetAttribute((const void*)gemm_2t<false, true>, cudaFuncAttributeMaxDynamicSharedMemorySize, SMEM_2T);
    cudaFuncSetAttribute((const void*)gemm_2t<true, false>, cudaFuncAttributeMaxDynamicSharedMemorySize, SMEM_2T);
    cudaFuncSetAttribute((const void*)gemm_w1,              cudaFuncAttributeMaxDynamicSharedMemorySize, SMEM_W);

    __half *xh,*Wvh,*Wvl,*Qh,*Kh,*Vth,*Ph;
    float *P;
    cudaGetSymbolAddress((void**)&xh, g_xh);
    cudaGetSymbolAddress((void**)&Wvh, g_Wvh); cudaGetSymbolAddress((void**)&Wvl, g_Wvl);
    cudaGetSymbolAddress((void**)&Qh, g_Qh);
    cudaGetSymbolAddress((void**)&Kh, g_Kh);
    cudaGetSymbolAddress((void**)&Vth, g_Vth);
    cudaGetSymbolAddress((void**)&P, g_P);
    cudaGetSymbolAddress((void**)&Ph, g_Ph);
    __half *Wqh,*Wql,*Wkh,*Wkl;
    cudaGetSymbolAddress((void**)&Wqh, g_Wqh); cudaGetSymbolAddress((void**)&Wql, g_Wql);
    cudaGetSymbolAddress((void**)&Wkh, g_Wkh); cudaGetSymbolAddress((void**)&Wkl, g_Wkl);

    const float scale = 1.0f / sqrtf((float)DIM);

    // 1) conversions
    to_h   <<<4096, 256>>>(x,  xh,  MTOT * DIM);
    to_hilo<<<2304, 256>>>(Wq, Wqh, Wql, DIM * DIM);
    to_hilo<<<2304, 256>>>(Wk, Wkh, Wkl, DIM * DIM);
    to_hilo<<<2304, 256>>>(Wv, Wvh, Wvl, DIM * DIM);

    // 2) fused Q&K projections (2-term, W hi+lo), fp16 out
    {
        dim3 g(DIM / BN, MTOT / BM, 2);
        gemm_2t<false, true><<<g, 256, SMEM_2T>>>(xh, nullptr, nullptr, nullptr,
                                                  DIM, DIM, DIM, DIM, 0);
    }
    // 3) Vt = (Wvh+Wvl)@x^T -> fp16 [DIM, MTOT]
    {
        dim3 g(MTOT / BN, DIM / BM, 1);
        gemm_2t<true, false><<<g, 256, SMEM_2T>>>(Wvh, xh, Wvl, Vth,
                                                  DIM, DIM, DIM, MTOT, 0);
    }
    // 4) scores = scale * Qh@Kh^T -> fp32 (wide 1-term)
    {
        dim3 g(SEQ / WBN, SEQ / BM, BATCH);
        gemm_w1<<<g, 256, SMEM_W>>>(Qh, Kh, P, DIM, DIM, DIM, SEQ,
                                    (long)SEQ * DIM, (long)SEQ * DIM, (long)SEQ * SEQ, scale);
    }
    // 5) softmax -> fp16
    softmax_rows<<<BATCH * SEQ, 256>>>(P, Ph);

    // 6) H = Ph@Vth^T -> fp32 out (wide 1-term)
    {
        dim3 g(DIM / WBN, SEQ / BM, BATCH);
        gemm_w1<<<g, 256, SMEM_W>>>(Ph, Vth, out, SEQ, SEQ, MTOT, DIM,
                                    (long)SEQ * SEQ, (long)SEQ, (long)SEQ * DIM, 1.0f);
    }
}

// round 8
// speedup vs baseline: 2.0693x; 1.2860x over previous
#include <cuda_runtime.h>
#include <cuda_fp16.h>
#include <math.h>
#include <stdint.h>

#define BATCH 8
#define SEQ   2048
#define DIM   768
#define MTOT  (BATCH*SEQ)

// ---------------- static device scratch ----------------
__device__ __half g_xh [(size_t)MTOT*DIM];
__device__ __half g_Wqh[DIM*DIM];
__device__ __half g_Wkh[DIM*DIM];
__device__ __half g_Wvh[DIM*DIM];
__device__ __half g_Qh [(size_t)MTOT*DIM];
__device__ __half g_Kh [(size_t)MTOT*DIM];
__device__ __half g_Vth[(size_t)DIM*MTOT];
__device__ __half g_Ph [(size_t)BATCH*SEQ*SEQ];

// ---------------- tiling ----------------
#define BM 128
#define WBN 256
#define BK 64
#define ROWB 144                       // 64 fp16 (128B) + 16B pad
#define TILE_SMEM (128*ROWB)           // 18432 B (A tile)
#define WB_TILE (256*ROWB)             // 36864 B (B tile)
#define WSTAGE (TILE_SMEM + WB_TILE)   // 55296 B
#define SMEM_W (3*WSTAGE)              // 165888 B

// ---------------- PTX helpers ----------------
__device__ __forceinline__ uint32_t smem_u32(const void* p) {
    uint32_t a;
    asm("{ .reg .u64 t; cvta.to.shared.u64 t, %1; cvt.u32.u64 %0, t; }" : "=r"(a) : "l"(p));
    return a;
}
__device__ __forceinline__ void cp_async16(uint32_t saddr, const void* gaddr) {
    asm volatile("cp.async.cg.shared.global [%0], [%1], 16;" :: "r"(saddr), "l"(gaddr));
}
__device__ __forceinline__ void cp_commit() {
    asm volatile("cp.async.commit_group;" ::: "memory");
}
template<int N> __device__ __forceinline__ void cp_wait() {
    asm volatile("cp.async.wait_group %0;" :: "n"(N) : "memory");
}
__device__ __forceinline__ void ldsm4(uint32_t* r, uint32_t addr) {
    asm volatile("ldmatrix.sync.aligned.m8n8.x4.shared.b16 {%0,%1,%2,%3}, [%4];"
                 : "=r"(r[0]), "=r"(r[1]), "=r"(r[2]), "=r"(r[3]) : "r"(addr));
}
__device__ __forceinline__ void mma16816(float* c, const uint32_t* a, const uint32_t* b) {
    asm volatile(
        "mma.sync.aligned.m16n8k16.row.col.f32.f16.f16.f32 "
        "{%0,%1,%2,%3}, {%4,%5,%6,%7}, {%8,%9}, {%0,%1,%2,%3};"
        : "+f"(c[0]), "+f"(c[1]), "+f"(c[2]), "+f"(c[3])
        : "r"(a[0]), "r"(a[1]), "r"(a[2]), "r"(a[3]), "r"(b[0]), "r"(b[1]));
}

// ============ wide 1-term GEMM: C[M,N] = scale * A@B^T, BM=128 x BN=256 ============
// OutHalf: write fp16 (Chp) else fp32 (Cf).
// QKF: gridDim.z=2 selects B/out as (Wqh->Qh)/(Wkh->Kh); Bp/Cf/Chp ignored, A fixed.
template<bool QKF, bool OutHalf>
__global__ void __launch_bounds__(256, 1) gemm_w1(
    const __half* __restrict__ A, const __half* __restrict__ Bp,
    float* __restrict__ Cf, __half* __restrict__ Chp,
    int K, int lda, int ldb, int ldc,
    long sA, long sB, long sC, float scale)
{
    constexpr int STAGES = 3;

    extern __shared__ char smem[];
    const uint32_t sb = smem_u32(smem);
    const int tid  = threadIdx.x;
    const int lane = tid & 31;
    const int wid  = tid >> 5;
    const int wm   = wid & 1;        // 2 x 64 rows
    const int wn   = wid >> 1;       // 4 x 64 cols
    const long z = blockIdx.z;

    const __half* AB;
    const __half* BB;
    __half* Ch = nullptr;
    float*  Cff = nullptr;
    if (QKF) {
        AB = A;
        BB = (z == 0) ? g_Wqh : g_Wkh;
        Ch = (z == 0) ? g_Qh  : g_Kh;
    } else {
        AB = A  + z * sA;
        BB = Bp + z * sB;
        if (OutHalf) Ch = Chp + z * sC;
        else         Cff = Cf + z * sC;
    }

    const int rowBase = blockIdx.y * BM;
    const int colBase = blockIdx.x * WBN;

    // cp.async: 12 chunks/thread (A: 1024 chunks, B: 2048 chunks)
    const __half* gsrc[12];
    uint32_t soff[12];
#pragma unroll
    for (int i = 0; i < 12; i++) {
        int idx = tid + i * 256;           // 0..3071
        if (idx < 1024) {
            int row = idx >> 3, ch = idx & 7;
            gsrc[i] = AB + (long)(rowBase + row) * lda + ch * 8;
            soff[i] = row * ROWB + ch * 16;
        } else {
            int w = idx - 1024;
            int row = w >> 3, ch = w & 7;
            gsrc[i] = BB + (long)(colBase + row) * ldb + ch * 8;
            soff[i] = TILE_SMEM + row * ROWB + ch * 16;
        }
    }

    const int j = lane >> 3, r = lane & 7;
    const uint32_t aOff = (uint32_t)(wm * 64 + (j & 1) * 8 + r) * ROWB + ((j >> 1) * 8) * 2;
    const uint32_t bOff = (uint32_t)(wn * 64 + (j >> 1) * 8 + r) * ROWB + ((j & 1) * 8) * 2;

    const int kTiles = K / BK;

#pragma unroll
    for (int s = 0; s < STAGES - 1; s++) {
        int k0 = s * BK;
#pragma unroll
        for (int i = 0; i < 12; i++)
            cp_async16(sb + s * WSTAGE + soff[i], gsrc[i] + k0);
        cp_commit();
    }

    float acc[4][8][4];
#pragma unroll
    for (int a = 0; a < 4; a++)
#pragma unroll
        for (int b = 0; b < 8; b++)
#pragma unroll
            for (int q = 0; q < 4; q++) acc[a][b][q] = 0.f;

    uint32_t ah[2][4][4], bh[2][8][2];

    for (int kt = 0; kt < kTiles; kt++) {
        cp_wait<STAGES - 2>();
        __syncthreads();

        {
            int ft = kt + STAGES - 1;
            if (ft < kTiles) {
                uint32_t sbase = sb + (ft % STAGES) * WSTAGE;
                int k0 = ft * BK;
#pragma unroll
                for (int i = 0; i < 12; i++)
                    cp_async16(sbase + soff[i], gsrc[i] + k0);
            }
            cp_commit();
        }

        const uint32_t stage = sb + (kt % STAGES) * WSTAGE;

#define WLOAD(ks, bi)                                                             \
        do {                                                                      \
            const uint32_t kb = (ks) * 32;                                        \
            _Pragma("unroll")                                                     \
            for (int mt = 0; mt < 4; mt++)                                        \
                ldsm4(ah[bi][mt], stage + aOff + mt * 16 * ROWB + kb);            \
            _Pragma("unroll")                                                     \
            for (int p = 0; p < 4; p++) {                                         \
                uint32_t t[4];                                                    \
                ldsm4(t, stage + TILE_SMEM + bOff + p * 16 * ROWB + kb);          \
                bh[bi][2 * p][0] = t[0]; bh[bi][2 * p][1] = t[1];                 \
                bh[bi][2 * p + 1][0] = t[2]; bh[bi][2 * p + 1][1] = t[3];         \
            }                                                                     \
        } while (0)

        WLOAD(0, 0);
#pragma unroll
        for (int ks = 0; ks < 4; ks++) {
            const int cur = ks & 1;
            if (ks < 3) WLOAD(ks + 1, (ks + 1) & 1);
#pragma unroll
            for (int mt = 0; mt < 4; mt++)
#pragma unroll
                for (int nt = 0; nt < 8; nt++)
                    mma16816(acc[mt][nt], ah[cur][mt], bh[cur][nt]);
        }
#undef WLOAD
    }

    const int mRow0 = rowBase + wm * 64 + (lane >> 2);
    const int nCol0 = colBase + wn * 64 + 2 * (lane & 3);

    if (QKF || OutHalf) {
#pragma unroll
        for (int mt = 0; mt < 4; mt++) {
#pragma unroll
            for (int nt = 0; nt < 8; nt++) {
                float* c = acc[mt][nt];
                long r0 = mRow0 + mt * 16;
                int  cc = nCol0 + nt * 8;
#pragma unroll
                for (int h = 0; h < 2; h++) {
                    __half2 hp;
                    hp.x = __float2half(c[2 * h] * scale);
                    hp.y = __float2half(c[2 * h + 1] * scale);
                    *(__half2*)(Ch + (r0 + 8 * h) * ldc + cc) = hp;
                }
            }
        }
    } else {
#pragma unroll
        for (int mt = 0; mt < 4; mt++) {
#pragma unroll
            for (int nt = 0; nt < 8; nt++) {
                float* c = acc[mt][nt];
                long r0 = mRow0 + mt * 16;
                int  cc = nCol0 + nt * 8;
                *(float2*)(Cff + r0 * ldc + cc)       = make_float2(c[0] * scale, c[1] * scale);
                *(float2*)(Cff + (r0 + 8) * ldc + cc) = make_float2(c[2] * scale, c[3] * scale);
            }
        }
    }
}

// ---------------- vectorized fp32 -> fp16 ----------------
__global__ void __launch_bounds__(256) to_h4(const float4* __restrict__ s,
                                             __half2* __restrict__ h, int n4)
{
    int i = blockIdx.x * 256 + threadIdx.x;
    if (i < n4) {
        float4 v = s[i];
        h[2 * i]     = __floats2half2_rn(v.x, v.y);
        h[2 * i + 1] = __floats2half2_rn(v.z, v.w);
    }
}

// ---------------- softmax: fp16 in -> fp16 out, in place ----------------
__global__ void __launch_bounds__(256) softmax_h(__half* __restrict__ Ph)
{
    __shared__ float red[256];
    __half* ph = Ph + (long)blockIdx.x * SEQ;
    const int t = threadIdx.x;

    float v[8];
    float m = -1e30f;
#pragma unroll
    for (int i = 0; i < 8; i++) {
        v[i] = __half2float(ph[t + i * 256]);
        m = fmaxf(m, v[i]);
    }
    red[t] = m; __syncthreads();
    for (int s = 128; s > 0; s >>= 1) {
        if (t < s) red[t] = fmaxf(red[t], red[t + s]);
        __syncthreads();
    }
    m = red[0]; __syncthreads();

    float sum = 0.f;
#pragma unroll
    for (int i = 0; i < 8; i++) { v[i] = __expf(v[i] - m); sum += v[i]; }
    red[t] = sum; __syncthreads();
    for (int s = 128; s > 0; s >>= 1) {
        if (t < s) red[t] += red[t + s];
        __syncthreads();
    }
    float inv = 1.0f / red[0];
#pragma unroll
    for (int i = 0; i < 8; i++)
        ph[t + i * 256] = __float2half(v[i] * inv);
}

// ---------------- host launcher ----------------
extern "C" void kernel_launch(void* const* d_in, const int* in_sizes, int n_in,
                              void* d_out, int out_size)
{
    const float* x  = (const float*)d_in[0];
    const float* Wq = (const float*)d_in[1];
    const float* Wk = (const float*)d_in[2];
    const float* Wv = (const float*)d_in[3];
    float* out = (float*)d_out;

    cudaFuncSetAttribute((const void*)gemm_w1<true,  true>,  cudaFuncAttributeMaxDynamicSharedMemorySize, SMEM_W);
    cudaFuncSetAttribute((const void*)gemm_w1<false, true>,  cudaFuncAttributeMaxDynamicSharedMemorySize, SMEM_W);
    cudaFuncSetAttribute((const void*)gemm_w1<false, false>, cudaFuncAttributeMaxDynamicSharedMemorySize, SMEM_W);

    __half *xh,*Wqh,*Wkh,*Wvh,*Qh,*Kh,*Vth,*Ph;
    cudaGetSymbolAddress((void**)&xh,  g_xh);
    cudaGetSymbolAddress((void**)&Wqh, g_Wqh);
    cudaGetSymbolAddress((void**)&Wkh, g_Wkh);
    cudaGetSymbolAddress((void**)&Wvh, g_Wvh);
    cudaGetSymbolAddress((void**)&Qh,  g_Qh);
    cudaGetSymbolAddress((void**)&Kh,  g_Kh);
    cudaGetSymbolAddress((void**)&Vth, g_Vth);
    cudaGetSymbolAddress((void**)&Ph,  g_Ph);

    const float scale = 1.0f / sqrtf((float)DIM);

    // 1) conversions (vectorized)
    to_h4<<<(MTOT * DIM / 4 + 255) / 256, 256>>>((const float4*)x,  (__half2*)xh,  MTOT * DIM / 4);
    to_h4<<<(DIM * DIM / 4 + 255) / 256, 256>>>((const float4*)Wq, (__half2*)Wqh, DIM * DIM / 4);
    to_h4<<<(DIM * DIM / 4 + 255) / 256, 256>>>((const float4*)Wk, (__half2*)Wkh, DIM * DIM / 4);
    to_h4<<<(DIM * DIM / 4 + 255) / 256, 256>>>((const float4*)Wv, (__half2*)Wvh, DIM * DIM / 4);

    // 2) fused Q&K projections: z=0 -> Qh, z=1 -> Kh (fp16 out)
    {
        dim3 g(DIM / WBN, MTOT / BM, 2);
        gemm_w1<true, true><<<g, 256, SMEM_W>>>(xh, nullptr, nullptr, nullptr,
                                                DIM, DIM, DIM, DIM, 0, 0, 0, 1.0f);
    }
    // 3) Vt = Wvh@xh^T -> fp16 [DIM, MTOT]
    {
        dim3 g(MTOT / WBN, DIM / BM, 1);
        gemm_w1<false, true><<<g, 256, SMEM_W>>>(Wvh, xh, nullptr, Vth,
                                                 DIM, DIM, DIM, MTOT, 0, 0, 0, 1.0f);
    }
    // 4) scores = scale * Qh@Kh^T -> fp16 directly
    {
        dim3 g(SEQ / WBN, SEQ / BM, BATCH);
        gemm_w1<false, true><<<g, 256, SMEM_W>>>(Qh, Kh, nullptr, Ph,
                                                 DIM, DIM, DIM, SEQ,
                                                 (long)SEQ * DIM, (long)SEQ * DIM,
                                                 (long)SEQ * SEQ, scale);
    }
    // 5) softmax in place on Ph (fp16)
    softmax_h<<<BATCH * SEQ, 256>>>(Ph);

    // 6) H = Ph@Vth^T -> fp32 out
    {
        dim3 g(DIM / WBN, SEQ / BM, BATCH);
        gemm_w1<false, false><<<g, 256, SMEM_W>>>(Ph, Vth, out, nullptr,
                                                  SEQ, SEQ, MTOT, DIM,
                                                  (long)SEQ * SEQ, (long)SEQ,
                                                  (long)SEQ * DIM, 1.0f);
    }
}

// round 10
// speedup vs baseline: 2.1725x; 1.0499x over previous
#include <cuda_runtime.h>
#include <cuda_fp16.h>
#include <math.h>
#include <stdint.h>

#define BATCH 8
#define SEQ   2048
#define DIM   768
#define MTOT  (BATCH*SEQ)

// ---------------- static device scratch ----------------
__device__ __half g_xh [(size_t)MTOT*DIM];
__device__ __half g_Wqh[DIM*DIM];
__device__ __half g_Wkh[DIM*DIM];
__device__ __half g_Wvh[DIM*DIM];
__device__ __half g_Qh [(size_t)MTOT*DIM];
__device__ __half g_Kh [(size_t)MTOT*DIM];
__device__ __half g_Vth[(size_t)DIM*MTOT];
__device__ __half g_Ph [(size_t)BATCH*SEQ*SEQ];

// ---------------- tiling ----------------
#define BM 128
#define WBN 256
#define BK 64
#define ROWB 144                       // 64 fp16 (128B) + 16B pad
#define TILE_SMEM (128*ROWB)           // 18432 B (A tile)
#define WB_TILE (256*ROWB)             // 36864 B (B tile)
#define WSTAGE (TILE_SMEM + WB_TILE)   // 55296 B
#define SMEM_W (3*WSTAGE)              // 165888 B

// ---------------- PTX helpers ----------------
__device__ __forceinline__ uint32_t smem_u32(const void* p) {
    uint32_t a;
    asm("{ .reg .u64 t; cvta.to.shared.u64 t, %1; cvt.u32.u64 %0, t; }" : "=r"(a) : "l"(p));
    return a;
}
__device__ __forceinline__ void cp_async16(uint32_t saddr, const void* gaddr) {
    asm volatile("cp.async.cg.shared.global [%0], [%1], 16;" :: "r"(saddr), "l"(gaddr));
}
__device__ __forceinline__ void cp_commit() {
    asm volatile("cp.async.commit_group;" ::: "memory");
}
template<int N> __device__ __forceinline__ void cp_wait() {
    asm volatile("cp.async.wait_group %0;" :: "n"(N) : "memory");
}
__device__ __forceinline__ void ldsm4(uint32_t* r, uint32_t addr) {
    asm volatile("ldmatrix.sync.aligned.m8n8.x4.shared.b16 {%0,%1,%2,%3}, [%4];"
                 : "=r"(r[0]), "=r"(r[1]), "=r"(r[2]), "=r"(r[3]) : "r"(addr));
}
__device__ __forceinline__ void mma16816(float* c, const uint32_t* a, const uint32_t* b) {
    asm volatile(
        "mma.sync.aligned.m16n8k16.row.col.f32.f16.f16.f32 "
        "{%0,%1,%2,%3}, {%4,%5,%6,%7}, {%8,%9}, {%0,%1,%2,%3};"
        : "+f"(c[0]), "+f"(c[1]), "+f"(c[2]), "+f"(c[3])
        : "r"(a[0]), "r"(a[1]), "r"(a[2]), "r"(a[3]), "r"(b[0]), "r"(b[1]));
}

// ======================= shared GEMM core (NT, fp16) =======================
// Computes acc = A[rowBase:+128, :K] @ B[colBase:+256, :K]^T with 3-stage pipeline.
struct GemmCore {
    const __half* gsrc[12];
    uint32_t soff[12];
    uint32_t aOff, bOff;

    __device__ __forceinline__ void init(const __half* AB, const __half* BB,
                                         int lda, int ldb, int rowBase, int colBase,
                                         int tid, int lane, int wm, int wn)
    {
#pragma unroll
        for (int i = 0; i < 12; i++) {
            int idx = tid + i * 256;
            if (idx < 1024) {
                int row = idx >> 3, ch = idx & 7;
                gsrc[i] = AB + (long)(rowBase + row) * lda + ch * 8;
                soff[i] = row * ROWB + ch * 16;
            } else {
                int w = idx - 1024;
                int row = w >> 3, ch = w & 7;
                gsrc[i] = BB + (long)(colBase + row) * ldb + ch * 8;
                soff[i] = TILE_SMEM + row * ROWB + ch * 16;
            }
        }
        const int j = lane >> 3, r = lane & 7;
        aOff = (uint32_t)(wm * 64 + (j & 1) * 8 + r) * ROWB + ((j >> 1) * 8) * 2;
        bOff = (uint32_t)(wn * 64 + (j >> 1) * 8 + r) * ROWB + ((j & 1) * 8) * 2;
    }

    __device__ __forceinline__ void run(uint32_t sb, int kTiles, float acc[4][8][4])
    {
#pragma unroll
        for (int s = 0; s < 2; s++) {
            int k0 = s * BK;
#pragma unroll
            for (int i = 0; i < 12; i++)
                cp_async16(sb + s * WSTAGE + soff[i], gsrc[i] + k0);
            cp_commit();
        }

        uint32_t ah[2][4][4], bh[2][8][2];

        for (int kt = 0; kt < kTiles; kt++) {
            cp_wait<1>();
            __syncthreads();

            {
                int ft = kt + 2;
                if (ft < kTiles) {
                    uint32_t sbase = sb + (ft % 3) * WSTAGE;
                    int k0 = ft * BK;
#pragma unroll
                    for (int i = 0; i < 12; i++)
                        cp_async16(sbase + soff[i], gsrc[i] + k0);
                }
                cp_commit();
            }

            const uint32_t stage = sb + (kt % 3) * WSTAGE;

#define WLOAD(ks, bi)                                                             \
            do {                                                                  \
                const uint32_t kb = (ks) * 32;                                    \
                _Pragma("unroll")                                                 \
                for (int mt = 0; mt < 4; mt++)                                    \
                    ldsm4(ah[bi][mt], stage + aOff + mt * 16 * ROWB + kb);        \
                _Pragma("unroll")                                                 \
                for (int p = 0; p < 4; p++) {                                     \
                    uint32_t t[4];                                                \
                    ldsm4(t, stage + TILE_SMEM + bOff + p * 16 * ROWB + kb);      \
                    bh[bi][2 * p][0] = t[0]; bh[bi][2 * p][1] = t[1];             \
                    bh[bi][2 * p + 1][0] = t[2]; bh[bi][2 * p + 1][1] = t[3];     \
                }                                                                 \
            } while (0)

            WLOAD(0, 0);
#pragma unroll
            for (int ks = 0; ks < 4; ks++) {
                const int cur = ks & 1;
                if (ks < 3) WLOAD(ks + 1, (ks + 1) & 1);
#pragma unroll
                for (int mt = 0; mt < 4; mt++)
#pragma unroll
                    for (int nt = 0; nt < 8; nt++)
                        mma16816(acc[mt][nt], ah[cur][mt], bh[cur][nt]);
            }
#undef WLOAD
        }
    }
};

// ============ fused projections: Q, K, Vt in ONE launch (1152 CTAs) ============
// blockIdx.x: [0,384) Q-tiles, [384,768) K-tiles, [768,1152) Vt-tiles.
__global__ void __launch_bounds__(256, 1) proj_fused()
{
    extern __shared__ char smem[];
    const uint32_t sb = smem_u32(smem);
    const int tid  = threadIdx.x;
    const int lane = tid & 31;
    const int wid  = tid >> 5;
    const int wm   = wid & 1;
    const int wn   = wid >> 1;

    const int bx = blockIdx.x;
    const int op  = bx / 384;          // 0:Q 1:K 2:Vt
    const int rem = bx % 384;

    const __half* AB;
    const __half* BB;
    __half* Ch;
    int lda, ldb, ldc, rowBase, colBase;

    if (op < 2) {
        // C[MTOT, DIM] = xh @ W^T ; n-tiles = DIM/WBN = 3, m-tiles = MTOT/BM = 128
        int nx = rem % 3, my = rem / 3;
        AB = g_xh; BB = (op == 0) ? g_Wqh : g_Wkh;
        Ch = (op == 0) ? g_Qh : g_Kh;
        lda = DIM; ldb = DIM; ldc = DIM;
        rowBase = my * BM; colBase = nx * WBN;
    } else {
        // Vt[DIM, MTOT] = Wvh @ xh^T ; n-tiles = MTOT/WBN = 64, m-tiles = DIM/BM = 6
        int nx = rem % 64, my = rem / 64;
        AB = g_Wvh; BB = g_xh; Ch = g_Vth;
        lda = DIM; ldb = DIM; ldc = MTOT;
        rowBase = my * BM; colBase = nx * WBN;
    }

    float acc[4][8][4];
#pragma unroll
    for (int a = 0; a < 4; a++)
#pragma unroll
        for (int b = 0; b < 8; b++)
#pragma unroll
            for (int q = 0; q < 4; q++) acc[a][b][q] = 0.f;

    GemmCore core;
    core.init(AB, BB, lda, ldb, rowBase, colBase, tid, lane, wm, wn);
    core.run(sb, DIM / BK, acc);

    const int mRow0 = rowBase + wm * 64 + (lane >> 2);
    const int nCol0 = colBase + wn * 64 + 2 * (lane & 3);
#pragma unroll
    for (int mt = 0; mt < 4; mt++) {
#pragma unroll
        for (int nt = 0; nt < 8; nt++) {
            float* c = acc[mt][nt];
            long r0 = mRow0 + mt * 16;
            int  cc = nCol0 + nt * 8;
#pragma unroll
            for (int h = 0; h < 2; h++) {
                __half2 hp;
                hp.x = __float2half(c[2 * h]);
                hp.y = __float2half(c[2 * h + 1]);
                *(__half2*)(Ch + (r0 + 8 * h) * (long)ldc + cc) = hp;
            }
        }
    }
}

// ============ wide 1-term GEMM (scores / AV): C = scale * A@B^T ============
template<bool OutHalf>
__global__ void __launch_bounds__(256, 1) gemm_w1(
    const __half* __restrict__ A, const __half* __restrict__ Bp,
    float* __restrict__ Cf, __half* __restrict__ Chp,
    int K, int lda, int ldb, int ldc,
    long sA, long sB, long sC, float scale)
{
    extern __shared__ char smem[];
    const uint32_t sb = smem_u32(smem);
    const int tid  = threadIdx.x;
    const int lane = tid & 31;
    const int wid  = tid >> 5;
    const int wm   = wid & 1;
    const int wn   = wid >> 1;
    const long z = blockIdx.z;

    const __half* AB = A  + z * sA;
    const __half* BB = Bp + z * sB;

    const int rowBase = blockIdx.y * BM;
    const int colBase = blockIdx.x * WBN;

    float acc[4][8][4];
#pragma unroll
    for (int a = 0; a < 4; a++)
#pragma unroll
        for (int b = 0; b < 8; b++)
#pragma unroll
            for (int q = 0; q < 4; q++) acc[a][b][q] = 0.f;

    GemmCore core;
    core.init(AB, BB, lda, ldb, rowBase, colBase, tid, lane, wm, wn);
    core.run(sb, K / BK, acc);

    const int mRow0 = rowBase + wm * 64 + (lane >> 2);
    const int nCol0 = colBase + wn * 64 + 2 * (lane & 3);

    if (OutHalf) {
        __half* Ch = Chp + z * sC;
#pragma unroll
        for (int mt = 0; mt < 4; mt++) {
#pragma unroll
            for (int nt = 0; nt < 8; nt++) {
                float* c = acc[mt][nt];
                long r0 = mRow0 + mt * 16;
                int  cc = nCol0 + nt * 8;
#pragma unroll
                for (int h = 0; h < 2; h++) {
                    __half2 hp;
                    hp.x = __float2half(c[2 * h] * scale);
                    hp.y = __float2half(c[2 * h + 1] * scale);
                    *(__half2*)(Ch + (r0 + 8 * h) * (long)ldc + cc) = hp;
                }
            }
        }
    } else {
        float* Cff = Cf + z * sC;
#pragma unroll
        for (int mt = 0; mt < 4; mt++) {
#pragma unroll
            for (int nt = 0; nt < 8; nt++) {
                float* c = acc[mt][nt];
                long r0 = mRow0 + mt * 16;
                int  cc = nCol0 + nt * 8;
                *(float2*)(Cff + r0 * (long)ldc + cc)       = make_float2(c[0] * scale, c[1] * scale);
                *(float2*)(Cff + (r0 + 8) * (long)ldc + cc) = make_float2(c[2] * scale, c[3] * scale);
            }
        }
    }
}

// ---------------- fused conversions: x, Wq, Wk, Wv -> fp16 in ONE launch ----------------
#define N4_X (MTOT*DIM/4)     // 3145728
#define N4_W (DIM*DIM/4)      // 147456
__global__ void __launch_bounds__(256) conv_fused(
    const float4* __restrict__ x, const float4* __restrict__ Wq,
    const float4* __restrict__ Wk, const float4* __restrict__ Wv)
{
    int i = blockIdx.x * 256 + threadIdx.x;
    const float4* s;
    __half2* d;
    int off;
    if (i < N4_X)                { s = x;  d = (__half2*)g_xh;  off = i; }
    else if (i < N4_X + N4_W)    { s = Wq; d = (__half2*)g_Wqh; off = i - N4_X; }
    else if (i < N4_X + 2*N4_W)  { s = Wk; d = (__half2*)g_Wkh; off = i - N4_X - N4_W; }
    else if (i < N4_X + 3*N4_W)  { s = Wv; d = (__half2*)g_Wvh; off = i - N4_X - 2*N4_W; }
    else return;
    float4 v = s[off];
    d[2 * off]     = __floats2half2_rn(v.x, v.y);
    d[2 * off + 1] = __floats2half2_rn(v.z, v.w);
}

// ---------------- softmax: fp16 in -> fp16 out, in place ----------------
__global__ void __launch_bounds__(256) softmax_h(__half* __restrict__ Ph)
{
    __shared__ float red[256];
    __half* ph = Ph + (long)blockIdx.x * SEQ;
    const int t = threadIdx.x;

    float v[8];
    float m = -1e30f;
#pragma unroll
    for (int i = 0; i < 8; i++) {
        v[i] = __half2float(ph[t + i * 256]);
        m = fmaxf(m, v[i]);
    }
    red[t] = m; __syncthreads();
    for (int s = 128; s > 0; s >>= 1) {
        if (t < s) red[t] = fmaxf(red[t], red[t + s]);
        __syncthreads();
    }
    m = red[0]; __syncthreads();

    float sum = 0.f;
#pragma unroll
    for (int i = 0; i < 8; i++) { v[i] = __expf(v[i] - m); sum += v[i]; }
    red[t] = sum; __syncthreads();
    for (int s = 128; s > 0; s >>= 1) {
        if (t < s) red[t] += red[t + s];
        __syncthreads();
    }
    float inv = 1.0f / red[0];
#pragma unroll
    for (int i = 0; i < 8; i++)
        ph[t + i * 256] = __float2half(v[i] * inv);
}

// ---------------- host launcher ----------------
extern "C" void kernel_launch(void* const* d_in, const int* in_sizes, int n_in,
                              void* d_out, int out_size)
{
    const float* x  = (const float*)d_in[0];
    const float* Wq = (const float*)d_in[1];
    const float* Wk = (const float*)d_in[2];
    const float* Wv = (const float*)d_in[3];
    float* out = (float*)d_out;

    cudaFuncSetAttribute((const void*)proj_fused,      cudaFuncAttributeMaxDynamicSharedMemorySize, SMEM_W);
    cudaFuncSetAttribute((const void*)gemm_w1<true>,   cudaFuncAttributeMaxDynamicSharedMemorySize, SMEM_W);
    cudaFuncSetAttribute((const void*)gemm_w1<false>,  cudaFuncAttributeMaxDynamicSharedMemorySize, SMEM_W);

    __half *Qh,*Kh,*Vth,*Ph;
    cudaGetSymbolAddress((void**)&Qh,  g_Qh);
    cudaGetSymbolAddress((void**)&Kh,  g_Kh);
    cudaGetSymbolAddress((void**)&Vth, g_Vth);
    cudaGetSymbolAddress((void**)&Ph,  g_Ph);

    const float scale = 1.0f / sqrtf((float)DIM);

    // 1) all conversions in one launch
    {
        int total = N4_X + 3 * N4_W;
        conv_fused<<<(total + 255) / 256, 256>>>((const float4*)x, (const float4*)Wq,
                                                 (const float4*)Wk, (const float4*)Wv);
    }

    // 2) Q-proj + K-proj + Vt in one 1152-CTA launch
    proj_fused<<<1152, 256, SMEM_W>>>();

    // 3) scores = scale * Qh@Kh^T -> fp16
    {
        dim3 g(SEQ / WBN, SEQ / BM, BATCH);
        gemm_w1<true><<<g, 256, SMEM_W>>>(Qh, Kh, nullptr, Ph,
                                          DIM, DIM, DIM, SEQ,
                                          (long)SEQ * DIM, (long)SEQ * DIM,
                                          (long)SEQ * SEQ, scale);
    }
    // 4) softmax in place on Ph
    softmax_h<<<BATCH * SEQ, 256>>>(Ph);

    // 5) H = Ph@Vth^T -> fp32 out
    {
        dim3 g(DIM / WBN, SEQ / BM, BATCH);
        gemm_w1<false><<<g, 256, SMEM_W>>>(Ph, Vth, out, nullptr,
                                           SEQ, SEQ, MTOT, DIM,
                                           (long)SEQ * SEQ, (long)SEQ,
                                           (long)SEQ * DIM, 1.0f);
    }
}

// round 11
// speedup vs baseline: 2.2439x; 1.0328x over previous
#include <cuda_runtime.h>
#include <cuda_fp16.h>
#include <math.h>
#include <stdint.h>

#define BATCH 8
#define SEQ   2048
#define DIM   768
#define MTOT  (BATCH*SEQ)

// ---------------- static device scratch ----------------
__device__ __half g_xh [(size_t)MTOT*DIM];
__device__ __half g_Wqh[DIM*DIM];
__device__ __half g_Wkh[DIM*DIM];
__device__ __half g_Wvh[DIM*DIM];
__device__ __half g_Qh [(size_t)MTOT*DIM];
__device__ __half g_Kh [(size_t)MTOT*DIM];
__device__ __half g_Vth[(size_t)DIM*MTOT];
__device__ __half g_Ph [(size_t)BATCH*SEQ*SEQ];

// ---------------- tiling ----------------
#define BM 128
#define WBN 256
#define BK 64
#define ROWB 144                       // 64 fp16 (128B) + 16B pad
#define TILE_SMEM (128*ROWB)           // 18432 B (A tile)
#define WB_TILE (256*ROWB)             // 36864 B (B tile)
#define WSTAGE (TILE_SMEM + WB_TILE)   // 55296 B
#define SMEM_W (3*WSTAGE)              // 165888 B

// ---------------- PTX helpers ----------------
__device__ __forceinline__ uint32_t smem_u32(const void* p) {
    uint32_t a;
    asm("{ .reg .u64 t; cvta.to.shared.u64 t, %1; cvt.u32.u64 %0, t; }" : "=r"(a) : "l"(p));
    return a;
}
__device__ __forceinline__ void cp_async16(uint32_t saddr, const void* gaddr) {
    asm volatile("cp.async.cg.shared.global [%0], [%1], 16;" :: "r"(saddr), "l"(gaddr));
}
__device__ __forceinline__ void cp_commit() {
    asm volatile("cp.async.commit_group;" ::: "memory");
}
template<int N> __device__ __forceinline__ void cp_wait() {
    asm volatile("cp.async.wait_group %0;" :: "n"(N) : "memory");
}
__device__ __forceinline__ void ldsm4(uint32_t* r, uint32_t addr) {
    asm volatile("ldmatrix.sync.aligned.m8n8.x4.shared.b16 {%0,%1,%2,%3}, [%4];"
                 : "=r"(r[0]), "=r"(r[1]), "=r"(r[2]), "=r"(r[3]) : "r"(addr));
}
__device__ __forceinline__ void mma16816(float* c, const uint32_t* a, const uint32_t* b) {
    asm volatile(
        "mma.sync.aligned.m16n8k16.row.col.f32.f16.f16.f32 "
        "{%0,%1,%2,%3}, {%4,%5,%6,%7}, {%8,%9}, {%0,%1,%2,%3};"
        : "+f"(c[0]), "+f"(c[1]), "+f"(c[2]), "+f"(c[3])
        : "r"(a[0]), "r"(a[1]), "r"(a[2]), "r"(a[3]), "r"(b[0]), "r"(b[1]));
}

// ======================= shared GEMM core (NT, fp16) =======================
struct GemmCore {
    const __half* gsrc[12];
    uint32_t soff[12];
    uint32_t aOff, bOff;

    __device__ __forceinline__ void init(const __half* AB, const __half* BB,
                                         int lda, int ldb, int rowBase, int colBase,
                                         int tid, int lane, int wm, int wn)
    {
#pragma unroll
        for (int i = 0; i < 12; i++) {
            int idx = tid + i * 256;
            if (idx < 1024) {
                int row = idx >> 3, ch = idx & 7;
                gsrc[i] = AB + (long)(rowBase + row) * lda + ch * 8;
                soff[i] = row * ROWB + ch * 16;
            } else {
                int w = idx - 1024;
                int row = w >> 3, ch = w & 7;
                gsrc[i] = BB + (long)(colBase + row) * ldb + ch * 8;
                soff[i] = TILE_SMEM + row * ROWB + ch * 16;
            }
        }
        const int j = lane >> 3, r = lane & 7;
        aOff = (uint32_t)(wm * 64 + (j & 1) * 8 + r) * ROWB + ((j >> 1) * 8) * 2;
        bOff = (uint32_t)(wn * 64 + (j >> 1) * 8 + r) * ROWB + ((j & 1) * 8) * 2;
    }

    __device__ __forceinline__ void run(uint32_t sb, int kTiles, float acc[4][8][4])
    {
#pragma unroll
        for (int s = 0; s < 2; s++) {
            int k0 = s * BK;
#pragma unroll
            for (int i = 0; i < 12; i++)
                cp_async16(sb + s * WSTAGE + soff[i], gsrc[i] + k0);
            cp_commit();
        }

        uint32_t ah[2][4][4], bh[2][8][2];

        for (int kt = 0; kt < kTiles; kt++) {
            cp_wait<1>();
            __syncthreads();

            {
                int ft = kt + 2;
                if (ft < kTiles) {
                    uint32_t sbase = sb + (ft % 3) * WSTAGE;
                    int k0 = ft * BK;
#pragma unroll
                    for (int i = 0; i < 12; i++)
                        cp_async16(sbase + soff[i], gsrc[i] + k0);
                }
                cp_commit();
            }

            const uint32_t stage = sb + (kt % 3) * WSTAGE;

#define WLOAD(ks, bi)                                                             \
            do {                                                                  \
                const uint32_t kb = (ks) * 32;                                    \
                _Pragma("unroll")                                                 \
                for (int mt = 0; mt < 4; mt++)                                    \
                    ldsm4(ah[bi][mt], stage + aOff + mt * 16 * ROWB + kb);        \
                _Pragma("unroll")                                                 \
                for (int p = 0; p < 4; p++) {                                     \
                    uint32_t t[4];                                                \
                    ldsm4(t, stage + TILE_SMEM + bOff + p * 16 * ROWB + kb);      \
                    bh[bi][2 * p][0] = t[0]; bh[bi][2 * p][1] = t[1];             \
                    bh[bi][2 * p + 1][0] = t[2]; bh[bi][2 * p + 1][1] = t[3];     \
                }                                                                 \
            } while (0)

            WLOAD(0, 0);
#pragma unroll
            for (int ks = 0; ks < 4; ks++) {
                const int cur = ks & 1;
                if (ks < 3) WLOAD(ks + 1, (ks + 1) & 1);
#pragma unroll
                for (int mt = 0; mt < 4; mt++)
#pragma unroll
                    for (int nt = 0; nt < 8; nt++)
                        mma16816(acc[mt][nt], ah[cur][mt], bh[cur][nt]);
            }
#undef WLOAD
        }
    }
};

// ============ fused projections: Q, K, Vt in ONE launch (1152 CTAs) ============
__global__ void __launch_bounds__(256, 1) proj_fused()
{
    extern __shared__ char smem[];
    const uint32_t sb = smem_u32(smem);
    const int tid  = threadIdx.x;
    const int lane = tid & 31;
    const int wid  = tid >> 5;
    const int wm   = wid & 1;
    const int wn   = wid >> 1;

    const int bx = blockIdx.x;
    const int op  = bx / 384;          // 0:Q 1:K 2:Vt
    const int rem = bx % 384;

    const __half* AB;
    const __half* BB;
    __half* Ch;
    int lda, ldb, ldc, rowBase, colBase;

    if (op < 2) {
        int nx = rem % 3, my = rem / 3;
        AB = g_xh; BB = (op == 0) ? g_Wqh : g_Wkh;
        Ch = (op == 0) ? g_Qh : g_Kh;
        lda = DIM; ldb = DIM; ldc = DIM;
        rowBase = my * BM; colBase = nx * WBN;
    } else {
        int nx = rem % 64, my = rem / 64;
        AB = g_Wvh; BB = g_xh; Ch = g_Vth;
        lda = DIM; ldb = DIM; ldc = MTOT;
        rowBase = my * BM; colBase = nx * WBN;
    }

    float acc[4][8][4];
#pragma unroll
    for (int a = 0; a < 4; a++)
#pragma unroll
        for (int b = 0; b < 8; b++)
#pragma unroll
            for (int q = 0; q < 4; q++) acc[a][b][q] = 0.f;

    GemmCore core;
    core.init(AB, BB, lda, ldb, rowBase, colBase, tid, lane, wm, wn);
    core.run(sb, DIM / BK, acc);

    const int mRow0 = rowBase + wm * 64 + (lane >> 2);
    const int nCol0 = colBase + wn * 64 + 2 * (lane & 3);
#pragma unroll
    for (int mt = 0; mt < 4; mt++) {
#pragma unroll
        for (int nt = 0; nt < 8; nt++) {
            float* c = acc[mt][nt];
            long r0 = mRow0 + mt * 16;
            int  cc = nCol0 + nt * 8;
#pragma unroll
            for (int h = 0; h < 2; h++) {
                __half2 hp;
                hp.x = __float2half(c[2 * h]);
                hp.y = __float2half(c[2 * h + 1]);
                *(__half2*)(Ch + (r0 + 8 * h) * (long)ldc + cc) = hp;
            }
        }
    }
}

// ============ wide 1-term GEMM (scores / AV): C = scale * A@B^T ============
template<bool OutHalf>
__global__ void __launch_bounds__(256, 1) gemm_w1(
    const __half* __restrict__ A, const __half* __restrict__ Bp,
    float* __restrict__ Cf, __half* __restrict__ Chp,
    int K, int lda, int ldb, int ldc,
    long sA, long sB, long sC, float scale)
{
    extern __shared__ char smem[];
    const uint32_t sb = smem_u32(smem);
    const int tid  = threadIdx.x;
    const int lane = tid & 31;
    const int wid  = tid >> 5;
    const int wm   = wid & 1;
    const int wn   = wid >> 1;
    const long z = blockIdx.z;

    const __half* AB = A  + z * sA;
    const __half* BB = Bp + z * sB;

    const int rowBase = blockIdx.y * BM;
    const int colBase = blockIdx.x * WBN;

    float acc[4][8][4];
#pragma unroll
    for (int a = 0; a < 4; a++)
#pragma unroll
        for (int b = 0; b < 8; b++)
#pragma unroll
            for (int q = 0; q < 4; q++) acc[a][b][q] = 0.f;

    GemmCore core;
    core.init(AB, BB, lda, ldb, rowBase, colBase, tid, lane, wm, wn);
    core.run(sb, K / BK, acc);

    const int mRow0 = rowBase + wm * 64 + (lane >> 2);
    const int nCol0 = colBase + wn * 64 + 2 * (lane & 3);

    if (OutHalf) {
        __half* Ch = Chp + z * sC;
#pragma unroll
        for (int mt = 0; mt < 4; mt++) {
#pragma unroll
            for (int nt = 0; nt < 8; nt++) {
                float* c = acc[mt][nt];
                long r0 = mRow0 + mt * 16;
                int  cc = nCol0 + nt * 8;
#pragma unroll
                for (int h = 0; h < 2; h++) {
                    __half2 hp;
                    hp.x = __float2half(c[2 * h] * scale);
                    hp.y = __float2half(c[2 * h + 1] * scale);
                    *(__half2*)(Ch + (r0 + 8 * h) * (long)ldc + cc) = hp;
                }
            }
        }
    } else {
        float* Cff = Cf + z * sC;
#pragma unroll
        for (int mt = 0; mt < 4; mt++) {
#pragma unroll
            for (int nt = 0; nt < 8; nt++) {
                float* c = acc[mt][nt];
                long r0 = mRow0 + mt * 16;
                int  cc = nCol0 + nt * 8;
                *(float2*)(Cff + r0 * (long)ldc + cc)       = make_float2(c[0] * scale, c[1] * scale);
                *(float2*)(Cff + (r0 + 8) * (long)ldc + cc) = make_float2(c[2] * scale, c[3] * scale);
            }
        }
    }
}

// ---------------- fused conversions ----------------
#define N4_X (MTOT*DIM/4)
#define N4_W (DIM*DIM/4)
__global__ void __launch_bounds__(256) conv_fused(
    const float4* __restrict__ x, const float4* __restrict__ Wq,
    const float4* __restrict__ Wk, const float4* __restrict__ Wv)
{
    int i = blockIdx.x * 256 + threadIdx.x;
    const float4* s;
    __half2* d;
    int off;
    if (i < N4_X)                { s = x;  d = (__half2*)g_xh;  off = i; }
    else if (i < N4_X + N4_W)    { s = Wq; d = (__half2*)g_Wqh; off = i - N4_X; }
    else if (i < N4_X + 2*N4_W)  { s = Wk; d = (__half2*)g_Wkh; off = i - N4_X - N4_W; }
    else if (i < N4_X + 3*N4_W)  { s = Wv; d = (__half2*)g_Wvh; off = i - N4_X - 2*N4_W; }
    else return;
    float4 v = s[off];
    d[2 * off]     = __floats2half2_rn(v.x, v.y);
    d[2 * off + 1] = __floats2half2_rn(v.z, v.w);
}

// ---------------- softmax: shuffle-based, vectorized, 2 barriers ----------------
// One block (256 thr) per row of 2048 fp16. Each thread owns one uint4 (8 halves).
__global__ void __launch_bounds__(256) softmax_h(__half* __restrict__ Ph)
{
    __shared__ float red[8];
    uint4* prow = (uint4*)(Ph + (long)blockIdx.x * SEQ);
    const int t    = threadIdx.x;
    const int lane = t & 31;
    const int wrp  = t >> 5;

    uint4 raw = prow[t];
    float2 f[4];
    f[0] = __half22float2(*(__half2*)&raw.x);
    f[1] = __half22float2(*(__half2*)&raw.y);
    f[2] = __half22float2(*(__half2*)&raw.z);
    f[3] = __half22float2(*(__half2*)&raw.w);

    // ---- max ----
    float m = f[0].x;
#pragma unroll
    for (int i = 0; i < 4; i++) { m = fmaxf(m, f[i].x); m = fmaxf(m, f[i].y); }
#pragma unroll
    for (int o = 16; o > 0; o >>= 1)
        m = fmaxf(m, __shfl_xor_sync(0xffffffffu, m, o));
    if (lane == 0) red[wrp] = m;
    __syncthreads();
    m = red[0];
#pragma unroll
    for (int w = 1; w < 8; w++) m = fmaxf(m, red[w]);

    // ---- exp + sum ----
    float sum = 0.f;
#pragma unroll
    for (int i = 0; i < 4; i++) {
        f[i].x = __expf(f[i].x - m); sum += f[i].x;
        f[i].y = __expf(f[i].y - m); sum += f[i].y;
    }
#pragma unroll
    for (int o = 16; o > 0; o >>= 1)
        sum += __shfl_xor_sync(0xffffffffu, sum, o);
    __syncthreads();                 // red[] reuse: all reads of max done
    if (lane == 0) red[wrp] = sum;
    __syncthreads();
    sum = red[0];
#pragma unroll
    for (int w = 1; w < 8; w++) sum += red[w];
    const float inv = 1.0f / sum;

    // ---- normalize + store ----
    uint4 outv;
    *(__half2*)&outv.x = __floats2half2_rn(f[0].x * inv, f[0].y * inv);
    *(__half2*)&outv.y = __floats2half2_rn(f[1].x * inv, f[1].y * inv);
    *(__half2*)&outv.z = __floats2half2_rn(f[2].x * inv, f[2].y * inv);
    *(__half2*)&outv.w = __floats2half2_rn(f[3].x * inv, f[3].y * inv);
    prow[t] = outv;
}

// ---------------- host launcher ----------------
extern "C" void kernel_launch(void* const* d_in, const int* in_sizes, int n_in,
                              void* d_out, int out_size)
{
    const float* x  = (const float*)d_in[0];
    const float* Wq = (const float*)d_in[1];
    const float* Wk = (const float*)d_in[2];
    const float* Wv = (const float*)d_in[3];
    float* out = (float*)d_out;

    cudaFuncSetAttribute((const void*)proj_fused,     cudaFuncAttributeMaxDynamicSharedMemorySize, SMEM_W);
    cudaFuncSetAttribute((const void*)gemm_w1<true>,  cudaFuncAttributeMaxDynamicSharedMemorySize, SMEM_W);
    cudaFuncSetAttribute((const void*)gemm_w1<false>, cudaFuncAttributeMaxDynamicSharedMemorySize, SMEM_W);

    __half *Qh,*Kh,*Vth,*Ph;
    cudaGetSymbolAddress((void**)&Qh,  g_Qh);
    cudaGetSymbolAddress((void**)&Kh,  g_Kh);
    cudaGetSymbolAddress((void**)&Vth, g_Vth);
    cudaGetSymbolAddress((void**)&Ph,  g_Ph);

    const float scale = 1.0f / sqrtf((float)DIM);

    // 1) all conversions in one launch
    {
        int total = N4_X + 3 * N4_W;
        conv_fused<<<(total + 255) / 256, 256>>>((const float4*)x, (const float4*)Wq,
                                                 (const float4*)Wk, (const float4*)Wv);
    }

    // 2) Q-proj + K-proj + Vt in one 1152-CTA launch
    proj_fused<<<1152, 256, SMEM_W>>>();

    // 3) scores = scale * Qh@Kh^T -> fp16
    {
        dim3 g(SEQ / WBN, SEQ / BM, BATCH);
        gemm_w1<true><<<g, 256, SMEM_W>>>(Qh, Kh, nullptr, Ph,
                                          DIM, DIM, DIM, SEQ,
                                          (long)SEQ * DIM, (long)SEQ * DIM,
                                          (long)SEQ * SEQ, scale);
    }
    // 4) softmax in place on Ph
    softmax_h<<<BATCH * SEQ, 256>>>(Ph);

    // 5) H = Ph@Vth^T -> fp32 out
    {
        dim3 g(DIM / WBN, SEQ / BM, BATCH);
        gemm_w1<false><<<g, 256, SMEM_W>>>(Ph, Vth, out, nullptr,
                                           SEQ, SEQ, MTOT, DIM,
                                           (long)SEQ * SEQ, (long)SEQ,
                                           (long)SEQ * DIM, 1.0f);
    }
}

// round 12
// speedup vs baseline: 2.2856x; 1.0186x over previous
#include <cuda_runtime.h>
#include <cuda_fp16.h>
#include <math.h>
#include <stdint.h>

#define BATCH 8
#define SEQ   2048
#define DIM   768
#define MTOT  (BATCH*SEQ)

// ---------------- static device scratch ----------------
__device__ __half g_xh [(size_t)MTOT*DIM];
__device__ __half g_Wqh[DIM*DIM];
__device__ __half g_Wkh[DIM*DIM];
__device__ __half g_Wvh[DIM*DIM];
__device__ __half g_Qh [(size_t)MTOT*DIM];
__device__ __half g_Kh [(size_t)MTOT*DIM];
__device__ __half g_Vth[(size_t)DIM*MTOT];
__device__ __half g_Ph [(size_t)BATCH*SEQ*SEQ];

// ---------------- tiling ----------------
#define BM 128
#define WBN 256
#define BK 128
#define ROWB 272                       // 128 fp16 (256B) + 16B pad (16 mod 128 -> conflict-free)
#define TILE_A (128*ROWB)              // 34816 B
#define TILE_B (256*ROWB)              // 69632 B
#define WSTAGE (TILE_A + TILE_B)       // 104448 B
#define SMEM_W (2*WSTAGE)              // 208896 B (2-stage)

// ---------------- PTX helpers ----------------
__device__ __forceinline__ uint32_t smem_u32(const void* p) {
    uint32_t a;
    asm("{ .reg .u64 t; cvta.to.shared.u64 t, %1; cvt.u32.u64 %0, t; }" : "=r"(a) : "l"(p));
    return a;
}
__device__ __forceinline__ void cp_async16(uint32_t saddr, const void* gaddr) {
    asm volatile("cp.async.cg.shared.global [%0], [%1], 16;" :: "r"(saddr), "l"(gaddr));
}
__device__ __forceinline__ void cp_commit() {
    asm volatile("cp.async.commit_group;" ::: "memory");
}
template<int N> __device__ __forceinline__ void cp_wait() {
    asm volatile("cp.async.wait_group %0;" :: "n"(N) : "memory");
}
__device__ __forceinline__ void ldsm4(uint32_t* r, uint32_t addr) {
    asm volatile("ldmatrix.sync.aligned.m8n8.x4.shared.b16 {%0,%1,%2,%3}, [%4];"
                 : "=r"(r[0]), "=r"(r[1]), "=r"(r[2]), "=r"(r[3]) : "r"(addr));
}
__device__ __forceinline__ void mma16816(float* c, const uint32_t* a, const uint32_t* b) {
    asm volatile(
        "mma.sync.aligned.m16n8k16.row.col.f32.f16.f16.f32 "
        "{%0,%1,%2,%3}, {%4,%5,%6,%7}, {%8,%9}, {%0,%1,%2,%3};"
        : "+f"(c[0]), "+f"(c[1]), "+f"(c[2]), "+f"(c[3])
        : "r"(a[0]), "r"(a[1]), "r"(a[2]), "r"(a[3]), "r"(b[0]), "r"(b[1]));
}

// ======================= shared GEMM core (NT, fp16, BK=128, 2-stage) =======================
// Linear cp.async addressing: chunk i of A has row = (tid>>4)+16i, fixed ch = tid&15.
struct GemmCore {
    const __half* pA;     // A base for this thread (row rowBase+tid>>4, col chunk tid&15)
    const __half* pB;
    int ldaStep, ldbStep; // 16*ld (halves) per chunk index
    uint32_t sA0, sB0;    // smem offsets for chunk 0
    uint32_t aOff, bOff;  // ldmatrix lane offsets

    __device__ __forceinline__ void init(const __half* AB, const __half* BB,
                                         int lda, int ldb, int rowBase, int colBase,
                                         int tid, int lane, int wm, int wn)
    {
        const int tr = tid >> 4;       // 0..15
        const int tc = tid & 15;       // 0..15 (16B chunk within 256B row)
        pA = AB + (long)(rowBase + tr) * lda + tc * 8;
        pB = BB + (long)(colBase + tr) * ldb + tc * 8;
        ldaStep = 16 * lda;
        ldbStep = 16 * ldb;
        sA0 = tr * ROWB + tc * 16;
        sB0 = TILE_A + tr * ROWB + tc * 16;

        const int j = lane >> 3, r = lane & 7;
        aOff = (uint32_t)(wm * 64 + (j & 1) * 8 + r) * ROWB + ((j >> 1) * 8) * 2;
        bOff = (uint32_t)(wn * 64 + (j >> 1) * 8 + r) * ROWB + ((j & 1) * 8) * 2;
    }

    __device__ __forceinline__ void load_stage(uint32_t sbase, int k0)
    {
#pragma unroll
        for (int i = 0; i < 8; i++)
            cp_async16(sbase + sA0 + i * (16 * ROWB), pA + k0 + i * ldaStep);
#pragma unroll
        for (int i = 0; i < 16; i++)
            cp_async16(sbase + sB0 + i * (16 * ROWB), pB + k0 + i * ldbStep);
    }

    __device__ __forceinline__ void run(uint32_t sb, int kTiles, float acc[4][8][4])
    {
        load_stage(sb, 0);
        cp_commit();

        uint32_t ah[2][4][4], bh[2][8][2];

        for (int kt = 0; kt < kTiles; kt++) {
            cp_wait<0>();          // this thread's stage-kt chunks arrived
            __syncthreads();       // all threads' chunks visible; prev compute done

            if (kt + 1 < kTiles) {
                load_stage(sb + ((kt + 1) & 1) * WSTAGE, (kt + 1) * BK);
                cp_commit();
            }

            const uint32_t stage = sb + (kt & 1) * WSTAGE;

#define WLOAD(ks, bi)                                                             \
            do {                                                                  \
                const uint32_t kb = (ks) * 32;                                    \
                _Pragma("unroll")                                                 \
                for (int mt = 0; mt < 4; mt++)                                    \
                    ldsm4(ah[bi][mt], stage + aOff + mt * 16 * ROWB + kb);        \
                _Pragma("unroll")                                                 \
                for (int p = 0; p < 4; p++) {                                     \
                    uint32_t t[4];                                                \
                    ldsm4(t, stage + TILE_A + bOff + p * 16 * ROWB + kb);         \
                    bh[bi][2 * p][0] = t[0]; bh[bi][2 * p][1] = t[1];             \
                    bh[bi][2 * p + 1][0] = t[2]; bh[bi][2 * p + 1][1] = t[3];     \
                }                                                                 \
            } while (0)

            WLOAD(0, 0);
#pragma unroll
            for (int ks = 0; ks < 8; ks++) {
                const int cur = ks & 1;
                if (ks < 7) WLOAD(ks + 1, (ks + 1) & 1);
#pragma unroll
                for (int mt = 0; mt < 4; mt++)
#pragma unroll
                    for (int nt = 0; nt < 8; nt++)
                        mma16816(acc[mt][nt], ah[cur][mt], bh[cur][nt]);
            }
#undef WLOAD
        }
    }
};

// ============ fused projections: Q, K, Vt in ONE launch (1152 CTAs) ============
__global__ void __launch_bounds__(256, 1) proj_fused()
{
    extern __shared__ char smem[];
    const uint32_t sb = smem_u32(smem);
    const int tid  = threadIdx.x;
    const int lane = tid & 31;
    const int wid  = tid >> 5;
    const int wm   = wid & 1;
    const int wn   = wid >> 1;

    const int bx = blockIdx.x;
    const int op  = bx / 384;          // 0:Q 1:K 2:Vt
    const int rem = bx % 384;

    const __half* AB;
    const __half* BB;
    __half* Ch;
    int lda, ldb, ldc, rowBase, colBase;

    if (op < 2) {
        int nx = rem % 3, my = rem / 3;
        AB = g_xh; BB = (op == 0) ? g_Wqh : g_Wkh;
        Ch = (op == 0) ? g_Qh : g_Kh;
        lda = DIM; ldb = DIM; ldc = DIM;
        rowBase = my * BM; colBase = nx * WBN;
    } else {
        int nx = rem % 64, my = rem / 64;
        AB = g_Wvh; BB = g_xh; Ch = g_Vth;
        lda = DIM; ldb = DIM; ldc = MTOT;
        rowBase = my * BM; colBase = nx * WBN;
    }

    float acc[4][8][4];
#pragma unroll
    for (int a = 0; a < 4; a++)
#pragma unroll
        for (int b = 0; b < 8; b++)
#pragma unroll
            for (int q = 0; q < 4; q++) acc[a][b][q] = 0.f;

    GemmCore core;
    core.init(AB, BB, lda, ldb, rowBase, colBase, tid, lane, wm, wn);
    core.run(sb, DIM / BK, acc);

    const int mRow0 = rowBase + wm * 64 + (lane >> 2);
    const int nCol0 = colBase + wn * 64 + 2 * (lane & 3);
#pragma unroll
    for (int mt = 0; mt < 4; mt++) {
#pragma unroll
        for (int nt = 0; nt < 8; nt++) {
            float* c = acc[mt][nt];
            long r0 = mRow0 + mt * 16;
            int  cc = nCol0 + nt * 8;
#pragma unroll
            for (int h = 0; h < 2; h++) {
                __half2 hp;
                hp.x = __float2half(c[2 * h]);
                hp.y = __float2half(c[2 * h + 1]);
                *(__half2*)(Ch + (r0 + 8 * h) * (long)ldc + cc) = hp;
            }
        }
    }
}

// ============ wide 1-term GEMM (scores / AV): C = scale * A@B^T ============
template<bool OutHalf>
__global__ void __launch_bounds__(256, 1) gemm_w1(
    const __half* __restrict__ A, const __half* __restrict__ Bp,
    float* __restrict__ Cf, __half* __restrict__ Chp,
    int K, int lda, int ldb, int ldc,
    long sA, long sB, long sC, float scale)
{
    extern __shared__ char smem[];
    const uint32_t sb = smem_u32(smem);
    const int tid  = threadIdx.x;
    const int lane = tid & 31;
    const int wid  = tid >> 5;
    const int wm   = wid & 1;
    const int wn   = wid >> 1;
    const long z = blockIdx.z;

    const __half* AB = A  + z * sA;
    const __half* BB = Bp + z * sB;

    const int rowBase = blockIdx.y * BM;
    const int colBase = blockIdx.x * WBN;

    float acc[4][8][4];
#pragma unroll
    for (int a = 0; a < 4; a++)
#pragma unroll
        for (int b = 0; b < 8; b++)
#pragma unroll
            for (int q = 0; q < 4; q++) acc[a][b][q] = 0.f;

    GemmCore core;
    core.init(AB, BB, lda, ldb, rowBase, colBase, tid, lane, wm, wn);
    core.run(sb, K / BK, acc);

    const int mRow0 = rowBase + wm * 64 + (lane >> 2);
    const int nCol0 = colBase + wn * 64 + 2 * (lane & 3);

    if (OutHalf) {
        __half* Ch = Chp + z * sC;
#pragma unroll
        for (int mt = 0; mt < 4; mt++) {
#pragma unroll
            for (int nt = 0; nt < 8; nt++) {
                float* c = acc[mt][nt];
                long r0 = mRow0 + mt * 16;
                int  cc = nCol0 + nt * 8;
#pragma unroll
                for (int h = 0; h < 2; h++) {
                    __half2 hp;
                    hp.x = __float2half(c[2 * h] * scale);
                    hp.y = __float2half(c[2 * h + 1] * scale);
                    *(__half2*)(Ch + (r0 + 8 * h) * (long)ldc + cc) = hp;
                }
            }
        }
    } else {
        float* Cff = Cf + z * sC;
#pragma unroll
        for (int mt = 0; mt < 4; mt++) {
#pragma unroll
            for (int nt = 0; nt < 8; nt++) {
                float* c = acc[mt][nt];
                long r0 = mRow0 + mt * 16;
                int  cc = nCol0 + nt * 8;
                *(float2*)(Cff + r0 * (long)ldc + cc)       = make_float2(c[0] * scale, c[1] * scale);
                *(float2*)(Cff + (r0 + 8) * (long)ldc + cc) = make_float2(c[2] * scale, c[3] * scale);
            }
        }
    }
}

// ---------------- fused conversions ----------------
#define N4_X (MTOT*DIM/4)
#define N4_W (DIM*DIM/4)
__global__ void __launch_bounds__(256) conv_fused(
    const float4* __restrict__ x, const float4* __restrict__ Wq,
    const float4* __restrict__ Wk, const float4* __restrict__ Wv)
{
    int i = blockIdx.x * 256 + threadIdx.x;
    const float4* s;
    __half2* d;
    int off;
    if (i < N4_X)                { s = x;  d = (__half2*)g_xh;  off = i; }
    else if (i < N4_X + N4_W)    { s = Wq; d = (__half2*)g_Wqh; off = i - N4_X; }
    else if (i < N4_X + 2*N4_W)  { s = Wk; d = (__half2*)g_Wkh; off = i - N4_X - N4_W; }
    else if (i < N4_X + 3*N4_W)  { s = Wv; d = (__half2*)g_Wvh; off = i - N4_X - 2*N4_W; }
    else return;
    float4 v = s[off];
    d[2 * off]     = __floats2half2_rn(v.x, v.y);
    d[2 * off + 1] = __floats2half2_rn(v.z, v.w);
}

// ---------------- softmax: shuffle-based, vectorized, 2 barriers ----------------
__global__ void __launch_bounds__(256) softmax_h(__half* __restrict__ Ph)
{
    __shared__ float red[8];
    uint4* prow = (uint4*)(Ph + (long)blockIdx.x * SEQ);
    const int t    = threadIdx.x;
    const int lane = t & 31;
    const int wrp  = t >> 5;

    uint4 raw = prow[t];
    float2 f[4];
    f[0] = __half22float2(*(__half2*)&raw.x);
    f[1] = __half22float2(*(__half2*)&raw.y);
    f[2] = __half22float2(*(__half2*)&raw.z);
    f[3] = __half22float2(*(__half2*)&raw.w);

    float m = f[0].x;
#pragma unroll
    for (int i = 0; i < 4; i++) { m = fmaxf(m, f[i].x); m = fmaxf(m, f[i].y); }
#pragma unroll
    for (int o = 16; o > 0; o >>= 1)
        m = fmaxf(m, __shfl_xor_sync(0xffffffffu, m, o));
    if (lane == 0) red[wrp] = m;
    __syncthreads();
    m = red[0];
#pragma unroll
    for (int w = 1; w < 8; w++) m = fmaxf(m, red[w]);

    float sum = 0.f;
#pragma unroll
    for (int i = 0; i < 4; i++) {
        f[i].x = __expf(f[i].x - m); sum += f[i].x;
        f[i].y = __expf(f[i].y - m); sum += f[i].y;
    }
#pragma unroll
    for (int o = 16; o > 0; o >>= 1)
        sum += __shfl_xor_sync(0xffffffffu, sum, o);
    __syncthreads();
    if (lane == 0) red[wrp] = sum;
    __syncthreads();
    sum = red[0];
#pragma unroll
    for (int w = 1; w < 8; w++) sum += red[w];
    const float inv = 1.0f / sum;

    uint4 outv;
    *(__half2*)&outv.x = __floats2half2_rn(f[0].x * inv, f[0].y * inv);
    *(__half2*)&outv.y = __floats2half2_rn(f[1].x * inv, f[1].y * inv);
    *(__half2*)&outv.z = __floats2half2_rn(f[2].x * inv, f[2].y * inv);
    *(__half2*)&outv.w = __floats2half2_rn(f[3].x * inv, f[3].y * inv);
    prow[t] = outv;
}

// ---------------- host launcher ----------------
extern "C" void kernel_launch(void* const* d_in, const int* in_sizes, int n_in,
                              void* d_out, int out_size)
{
    const float* x  = (const float*)d_in[0];
    const float* Wq = (const float*)d_in[1];
    const float* Wk = (const float*)d_in[2];
    const float* Wv = (const float*)d_in[3];
    float* out = (float*)d_out;

    cudaFuncSetAttribute((const void*)proj_fused,     cudaFuncAttributeMaxDynamicSharedMemorySize, SMEM_W);
    cudaFuncSetAttribute((const void*)gemm_w1<true>,  cudaFuncAttributeMaxDynamicSharedMemorySize, SMEM_W);
    cudaFuncSetAttribute((const void*)gemm_w1<false>, cudaFuncAttributeMaxDynamicSharedMemorySize, SMEM_W);

    __half *Qh,*Kh,*Vth,*Ph;
    cudaGetSymbolAddress((void**)&Qh,  g_Qh);
    cudaGetSymbolAddress((void**)&Kh,  g_Kh);
    cudaGetSymbolAddress((void**)&Vth, g_Vth);
    cudaGetSymbolAddress((void**)&Ph,  g_Ph);

    const float scale = 1.0f / sqrtf((float)DIM);

    // 1) all conversions in one launch
    {
        int total = N4_X + 3 * N4_W;
        conv_fused<<<(total + 255) / 256, 256>>>((const float4*)x, (const float4*)Wq,
                                                 (const float4*)Wk, (const float4*)Wv);
    }

    // 2) Q-proj + K-proj + Vt in one 1152-CTA launch
    proj_fused<<<1152, 256, SMEM_W>>>();

    // 3) scores = scale * Qh@Kh^T -> fp16
    {
        dim3 g(SEQ / WBN, SEQ / BM, BATCH);
        gemm_w1<true><<<g, 256, SMEM_W>>>(Qh, Kh, nullptr, Ph,
                                          DIM, DIM, DIM, SEQ,
                                          (long)SEQ * DIM, (long)SEQ * DIM,
                                          (long)SEQ * SEQ, scale);
    }
    // 4) softmax in place on Ph
    softmax_h<<<BATCH * SEQ, 256>>>(Ph);

    // 5) H = Ph@Vth^T -> fp32 out
    {
        dim3 g(DIM / WBN, SEQ / BM, BATCH);
        gemm_w1<false><<<g, 256, SMEM_W>>>(Ph, Vth, out, nullptr,
                                           SEQ, SEQ, MTOT, DIM,
                                           (long)SEQ * SEQ, (long)SEQ,
                                           (long)SEQ * DIM, 1.0f);
    }
}

// round 13
// speedup vs baseline: 2.3805x; 1.0415x over previous
#include <cuda_runtime.h>
#include <cuda_fp16.h>
#include <math.h>
#include <stdint.h>

#define BATCH 8
#define SEQ   2048
#define DIM   768
#define MTOT  (BATCH*SEQ)

// ---------------- static device scratch ----------------
__device__ __half g_xh [(size_t)MTOT*DIM];
__device__ __half g_Wqh[DIM*DIM];
__device__ __half g_Wkh[DIM*DIM];
__device__ __half g_Wvh[DIM*DIM];
__device__ __half g_Qh [(size_t)MTOT*DIM];
__device__ __half g_Kh [(size_t)MTOT*DIM];
__device__ __half g_Vth[(size_t)DIM*MTOT];
__device__ __half g_Ph [(size_t)BATCH*SEQ*SEQ];   // exp(s) unnormalized
__device__ float  g_rowsum[MTOT];                  // per q-row sum of exp(s)

// ---------------- tiling ----------------
#define BM 128
#define WBN 256
#define BK 128
#define ROWB 272                       // 128 fp16 (256B) + 16B pad
#define TILE_A (128*ROWB)              // 34816 B
#define TILE_B (256*ROWB)              // 69632 B
#define WSTAGE (TILE_A + TILE_B)       // 104448 B
#define SMEM_W (2*WSTAGE)              // 208896 B

// ---------------- PTX helpers ----------------
__device__ __forceinline__ uint32_t smem_u32(const void* p) {
    uint32_t a;
    asm("{ .reg .u64 t; cvta.to.shared.u64 t, %1; cvt.u32.u64 %0, t; }" : "=r"(a) : "l"(p));
    return a;
}
__device__ __forceinline__ void cp_async16(uint32_t saddr, const void* gaddr) {
    asm volatile("cp.async.cg.shared.global [%0], [%1], 16;" :: "r"(saddr), "l"(gaddr));
}
__device__ __forceinline__ void cp_commit() {
    asm volatile("cp.async.commit_group;" ::: "memory");
}
template<int N> __device__ __forceinline__ void cp_wait() {
    asm volatile("cp.async.wait_group %0;" :: "n"(N) : "memory");
}
__device__ __forceinline__ void ldsm4(uint32_t* r, uint32_t addr) {
    asm volatile("ldmatrix.sync.aligned.m8n8.x4.shared.b16 {%0,%1,%2,%3}, [%4];"
                 : "=r"(r[0]), "=r"(r[1]), "=r"(r[2]), "=r"(r[3]) : "r"(addr));
}
__device__ __forceinline__ void mma16816(float* c, const uint32_t* a, const uint32_t* b) {
    asm volatile(
        "mma.sync.aligned.m16n8k16.row.col.f32.f16.f16.f32 "
        "{%0,%1,%2,%3}, {%4,%5,%6,%7}, {%8,%9}, {%0,%1,%2,%3};"
        : "+f"(c[0]), "+f"(c[1]), "+f"(c[2]), "+f"(c[3])
        : "r"(a[0]), "r"(a[1]), "r"(a[2]), "r"(a[3]), "r"(b[0]), "r"(b[1]));
}

// ======================= shared GEMM core (NT, fp16, BK=128, 2-stage) =======================
struct GemmCore {
    const __half* pA;
    const __half* pB;
    int ldaStep, ldbStep;
    uint32_t sA0, sB0;
    uint32_t aOff, bOff;

    __device__ __forceinline__ void init(const __half* AB, const __half* BB,
                                         int lda, int ldb, int rowBase, int colBase,
                                         int tid, int lane, int wm, int wn)
    {
        const int tr = tid >> 4;
        const int tc = tid & 15;
        pA = AB + (long)(rowBase + tr) * lda + tc * 8;
        pB = BB + (long)(colBase + tr) * ldb + tc * 8;
        ldaStep = 16 * lda;
        ldbStep = 16 * ldb;
        sA0 = tr * ROWB + tc * 16;
        sB0 = TILE_A + tr * ROWB + tc * 16;

        const int j = lane >> 3, r = lane & 7;
        aOff = (uint32_t)(wm * 64 + (j & 1) * 8 + r) * ROWB + ((j >> 1) * 8) * 2;
        bOff = (uint32_t)(wn * 64 + (j >> 1) * 8 + r) * ROWB + ((j & 1) * 8) * 2;
    }

    __device__ __forceinline__ void load_stage(uint32_t sbase, int k0)
    {
#pragma unroll
        for (int i = 0; i < 8; i++)
            cp_async16(sbase + sA0 + i * (16 * ROWB), pA + k0 + i * ldaStep);
#pragma unroll
        for (int i = 0; i < 16; i++)
            cp_async16(sbase + sB0 + i * (16 * ROWB), pB + k0 + i * ldbStep);
    }

    __device__ __forceinline__ void run(uint32_t sb, int kTiles, float acc[4][8][4])
    {
        load_stage(sb, 0);
        cp_commit();

        uint32_t ah[2][4][4], bh[2][8][2];

        for (int kt = 0; kt < kTiles; kt++) {
            cp_wait<0>();
            __syncthreads();

            if (kt + 1 < kTiles) {
                load_stage(sb + ((kt + 1) & 1) * WSTAGE, (kt + 1) * BK);
                cp_commit();
            }

            const uint32_t stage = sb + (kt & 1) * WSTAGE;

#define WLOAD(ks, bi)                                                             \
            do {                                                                  \
                const uint32_t kb = (ks) * 32;                                    \
                _Pragma("unroll")                                                 \
                for (int mt = 0; mt < 4; mt++)                                    \
                    ldsm4(ah[bi][mt], stage + aOff + mt * 16 * ROWB + kb);        \
                _Pragma("unroll")                                                 \
                for (int p = 0; p < 4; p++) {                                     \
                    uint32_t t[4];                                                \
                    ldsm4(t, stage + TILE_A + bOff + p * 16 * ROWB + kb);         \
                    bh[bi][2 * p][0] = t[0]; bh[bi][2 * p][1] = t[1];             \
                    bh[bi][2 * p + 1][0] = t[2]; bh[bi][2 * p + 1][1] = t[3];     \
                }                                                                 \
            } while (0)

            WLOAD(0, 0);
#pragma unroll
            for (int ks = 0; ks < 8; ks++) {
                const int cur = ks & 1;
                if (ks < 7) WLOAD(ks + 1, (ks + 1) & 1);
#pragma unroll
                for (int mt = 0; mt < 4; mt++)
#pragma unroll
                    for (int nt = 0; nt < 8; nt++)
                        mma16816(acc[mt][nt], ah[cur][mt], bh[cur][nt]);
            }
#undef WLOAD
        }
    }
};

// ============ fused projections: Q, K, Vt in ONE launch (1152 CTAs) ============
__global__ void __launch_bounds__(256, 1) proj_fused()
{
    extern __shared__ char smem[];
    const uint32_t sb = smem_u32(smem);
    const int tid  = threadIdx.x;
    const int lane = tid & 31;
    const int wid  = tid >> 5;
    const int wm   = wid & 1;
    const int wn   = wid >> 1;

    const int bx = blockIdx.x;
    const int op  = bx / 384;          // 0:Q 1:K 2:Vt
    const int rem = bx % 384;

    const __half* AB;
    const __half* BB;
    __half* Ch;
    int lda, ldb, ldc, rowBase, colBase;

    if (op < 2) {
        int nx = rem % 3, my = rem / 3;
        AB = g_xh; BB = (op == 0) ? g_Wqh : g_Wkh;
        Ch = (op == 0) ? g_Qh : g_Kh;
        lda = DIM; ldb = DIM; ldc = DIM;
        rowBase = my * BM; colBase = nx * WBN;
    } else {
        int nx = rem % 64, my = rem / 64;
        AB = g_Wvh; BB = g_xh; Ch = g_Vth;
        lda = DIM; ldb = DIM; ldc = MTOT;
        rowBase = my * BM; colBase = nx * WBN;
    }

    float acc[4][8][4];
#pragma unroll
    for (int a = 0; a < 4; a++)
#pragma unroll
        for (int b = 0; b < 8; b++)
#pragma unroll
            for (int q = 0; q < 4; q++) acc[a][b][q] = 0.f;

    GemmCore core;
    core.init(AB, BB, lda, ldb, rowBase, colBase, tid, lane, wm, wn);
    core.run(sb, DIM / BK, acc);

    const int mRow0 = rowBase + wm * 64 + (lane >> 2);
    const int nCol0 = colBase + wn * 64 + 2 * (lane & 3);
#pragma unroll
    for (int mt = 0; mt < 4; mt++) {
#pragma unroll
        for (int nt = 0; nt < 8; nt++) {
            float* c = acc[mt][nt];
            long r0 = mRow0 + mt * 16;
            int  cc = nCol0 + nt * 8;
#pragma unroll
            for (int h = 0; h < 2; h++) {
                __half2 hp;
                hp.x = __float2half(c[2 * h]);
                hp.y = __float2half(c[2 * h + 1]);
                *(__half2*)(Ch + (r0 + 8 * h) * (long)ldc + cc) = hp;
            }
        }
    }
}

// ============ scores GEMM: Ph = exp(scale * Qh@Kh^T), accumulate row sums ============
__global__ void __launch_bounds__(256, 1) gemm_scores(float scale)
{
    extern __shared__ char smem[];
    const uint32_t sb = smem_u32(smem);
    const int tid  = threadIdx.x;
    const int lane = tid & 31;
    const int wid  = tid >> 5;
    const int wm   = wid & 1;
    const int wn   = wid >> 1;
    const long z = blockIdx.z;

    const __half* AB = g_Qh + z * (long)SEQ * DIM;
    const __half* BB = g_Kh + z * (long)SEQ * DIM;

    const int rowBase = blockIdx.y * BM;
    const int colBase = blockIdx.x * WBN;

    float acc[4][8][4];
#pragma unroll
    for (int a = 0; a < 4; a++)
#pragma unroll
        for (int b = 0; b < 8; b++)
#pragma unroll
            for (int q = 0; q < 4; q++) acc[a][b][q] = 0.f;

    GemmCore core;
    core.init(AB, BB, DIM, DIM, rowBase, colBase, tid, lane, wm, wn);
    core.run(sb, DIM / BK, acc);

    __half* Ch = g_Ph + z * (long)SEQ * SEQ;
    const int mRow0 = rowBase + wm * 64 + (lane >> 2);
    const int nCol0 = colBase + wn * 64 + 2 * (lane & 3);

    float rsum[4][2];   // per (mt, h) row partial over this thread's 16 cols
#pragma unroll
    for (int mt = 0; mt < 4; mt++) { rsum[mt][0] = 0.f; rsum[mt][1] = 0.f; }

#pragma unroll
    for (int mt = 0; mt < 4; mt++) {
#pragma unroll
        for (int nt = 0; nt < 8; nt++) {
            float* c = acc[mt][nt];
            long r0 = mRow0 + mt * 16;
            int  cc = nCol0 + nt * 8;
#pragma unroll
            for (int h = 0; h < 2; h++) {
                float e0 = __expf(c[2 * h]     * scale);
                float e1 = __expf(c[2 * h + 1] * scale);
                rsum[mt][h] += e0 + e1;
                __half2 hp = __floats2half2_rn(e0, e1);
                *(__half2*)(Ch + (r0 + 8 * h) * (long)SEQ + cc) = hp;
            }
        }
    }

    // quad-reduce (lanes 4k..4k+3 share a row) then one atomic per row per warp
#pragma unroll
    for (int mt = 0; mt < 4; mt++) {
#pragma unroll
        for (int h = 0; h < 2; h++) {
            float p = rsum[mt][h];
            p += __shfl_xor_sync(0xffffffffu, p, 1);
            p += __shfl_xor_sync(0xffffffffu, p, 2);
            if ((lane & 3) == 0) {
                long row = z * SEQ + mRow0 + mt * 16 + 8 * h;
                atomicAdd(&g_rowsum[row], p);
            }
        }
    }
}

// ============ AV GEMM: out = (Ph @ Vth^T) / rowsum ============
__global__ void __launch_bounds__(256, 1) gemm_av(float* __restrict__ out)
{
    extern __shared__ char smem[];
    const uint32_t sb = smem_u32(smem);
    const int tid  = threadIdx.x;
    const int lane = tid & 31;
    const int wid  = tid >> 5;
    const int wm   = wid & 1;
    const int wn   = wid >> 1;
    const long z = blockIdx.z;

    const __half* AB = g_Ph  + z * (long)SEQ * SEQ;
    const __half* BB = g_Vth + z * (long)SEQ;       // Vt columns for this batch

    const int rowBase = blockIdx.y * BM;
    const int colBase = blockIdx.x * WBN;

    float acc[4][8][4];
#pragma unroll
    for (int a = 0; a < 4; a++)
#pragma unroll
        for (int b = 0; b < 8; b++)
#pragma unroll
            for (int q = 0; q < 4; q++) acc[a][b][q] = 0.f;

    GemmCore core;
    core.init(AB, BB, SEQ, MTOT, rowBase, colBase, tid, lane, wm, wn);
    core.run(sb, SEQ / BK, acc);

    float* Cff = out + z * (long)SEQ * DIM;
    const int mRow0 = rowBase + wm * 64 + (lane >> 2);
    const int nCol0 = colBase + wn * 64 + 2 * (lane & 3);

    float inv[4][2];
#pragma unroll
    for (int mt = 0; mt < 4; mt++)
#pragma unroll
        for (int h = 0; h < 2; h++)
            inv[mt][h] = 1.0f / g_rowsum[z * SEQ + mRow0 + mt * 16 + 8 * h];

#pragma unroll
    for (int mt = 0; mt < 4; mt++) {
#pragma unroll
        for (int nt = 0; nt < 8; nt++) {
            float* c = acc[mt][nt];
            long r0 = mRow0 + mt * 16;
            int  cc = nCol0 + nt * 8;
            *(float2*)(Cff + r0 * (long)DIM + cc) =
                make_float2(c[0] * inv[mt][0], c[1] * inv[mt][0]);
            *(float2*)(Cff + (r0 + 8) * (long)DIM + cc) =
                make_float2(c[2] * inv[mt][1], c[3] * inv[mt][1]);
        }
    }
}

// ---------------- fused conversions + rowsum zeroing ----------------
#define N4_X (MTOT*DIM/4)
#define N4_W (DIM*DIM/4)
#define N4_S (MTOT/4)
__global__ void __launch_bounds__(256) conv_fused(
    const float4* __restrict__ x, const float4* __restrict__ Wq,
    const float4* __restrict__ Wk, const float4* __restrict__ Wv)
{
    int i = blockIdx.x * 256 + threadIdx.x;
    const float4* s;
    __half2* d;
    int off;
    if (i < N4_X)                { s = x;  d = (__half2*)g_xh;  off = i; }
    else if (i < N4_X + N4_W)    { s = Wq; d = (__half2*)g_Wqh; off = i - N4_X; }
    else if (i < N4_X + 2*N4_W)  { s = Wk; d = (__half2*)g_Wkh; off = i - N4_X - N4_W; }
    else if (i < N4_X + 3*N4_W)  { s = Wv; d = (__half2*)g_Wvh; off = i - N4_X - 2*N4_W; }
    else if (i < N4_X + 3*N4_W + N4_S) {
        int o = i - N4_X - 3*N4_W;
        ((float4*)g_rowsum)[o] = make_float4(0.f, 0.f, 0.f, 0.f);
        return;
    }
    else return;
    float4 v = s[off];
    d[2 * off]     = __floats2half2_rn(v.x, v.y);
    d[2 * off + 1] = __floats2half2_rn(v.z, v.w);
}

// ---------------- host launcher ----------------
extern "C" void kernel_launch(void* const* d_in, const int* in_sizes, int n_in,
                              void* d_out, int out_size)
{
    const float* x  = (const float*)d_in[0];
    const float* Wq = (const float*)d_in[1];
    const float* Wk = (const float*)d_in[2];
    const float* Wv = (const float*)d_in[3];
    float* out = (float*)d_out;

    cudaFuncSetAttribute((const void*)proj_fused,  cudaFuncAttributeMaxDynamicSharedMemorySize, SMEM_W);
    cudaFuncSetAttribute((const void*)gemm_scores, cudaFuncAttributeMaxDynamicSharedMemorySize, SMEM_W);
    cudaFuncSetAttribute((const void*)gemm_av,     cudaFuncAttributeMaxDynamicSharedMemorySize, SMEM_W);

    const float scale = 1.0f / sqrtf((float)DIM);

    // 1) conversions + rowsum zero, one launch
    {
        int total = N4_X + 3 * N4_W + N4_S;
        conv_fused<<<(total + 255) / 256, 256>>>((const float4*)x, (const float4*)Wq,
                                                 (const float4*)Wk, (const float4*)Wv);
    }

    // 2) Q-proj + K-proj + Vt in one 1152-CTA launch
    proj_fused<<<1152, 256, SMEM_W>>>();

    // 3) scores -> exp(s) fp16 + row sums (softmax max-free, fused)
    {
        dim3 g(SEQ / WBN, SEQ / BM, BATCH);
        gemm_scores<<<g, 256, SMEM_W>>>(scale);
    }

    // 4) H = (Ph @ Vth^T) / rowsum -> fp32 out
    {
        dim3 g(DIM / WBN, SEQ / BM, BATCH);
        gemm_av<<<g, 256, SMEM_W>>>(out);
    }
}

// round 14
// speedup vs baseline: 2.4911x; 1.0465x over previous
#include <cuda_runtime.h>
#include <cuda_fp16.h>
#include <math.h>
#include <stdint.h>

#define BATCH 8
#define SEQ   2048
#define DIM   768
#define MTOT  (BATCH*SEQ)

// ---------------- static device scratch ----------------
__device__ __half g_xh [(size_t)MTOT*DIM];
__device__ __half g_Wqh[DIM*DIM];
__device__ __half g_Wkh[DIM*DIM];
__device__ __half g_Wvh[DIM*DIM];
__device__ __half g_Qh [(size_t)MTOT*DIM];
__device__ __half g_Kh [(size_t)MTOT*DIM];
__device__ __half g_Vth[(size_t)DIM*MTOT];
__device__ __half g_Ph [(size_t)BATCH*SEQ*SEQ];   // exp(s) unnormalized
__device__ float  g_rowsum[MTOT];                  // per q-row sum of exp(s)

// ---------------- tiling: 128x128x64, 3-stage, 2 CTAs/SM ----------------
#define BM 128
#define BN 128
#define BK 64
#define ROWB 144                       // 64 fp16 (128B) + 16B pad
#define TILE_A (128*ROWB)              // 18432 B
#define TILE_B (128*ROWB)              // 18432 B
#define WSTAGE (TILE_A + TILE_B)       // 36864 B
#define SMEM_G (3*WSTAGE)              // 110592 B -> 2 CTAs/SM

// ---------------- PTX helpers ----------------
__device__ __forceinline__ uint32_t smem_u32(const void* p) {
    uint32_t a;
    asm("{ .reg .u64 t; cvta.to.shared.u64 t, %1; cvt.u32.u64 %0, t; }" : "=r"(a) : "l"(p));
    return a;
}
__device__ __forceinline__ void cp_async16(uint32_t saddr, const void* gaddr) {
    asm volatile("cp.async.cg.shared.global [%0], [%1], 16;" :: "r"(saddr), "l"(gaddr));
}
__device__ __forceinline__ void cp_commit() {
    asm volatile("cp.async.commit_group;" ::: "memory");
}
template<int N> __device__ __forceinline__ void cp_wait() {
    asm volatile("cp.async.wait_group %0;" :: "n"(N) : "memory");
}
__device__ __forceinline__ void ldsm4(uint32_t* r, uint32_t addr) {
    asm volatile("ldmatrix.sync.aligned.m8n8.x4.shared.b16 {%0,%1,%2,%3}, [%4];"
                 : "=r"(r[0]), "=r"(r[1]), "=r"(r[2]), "=r"(r[3]) : "r"(addr));
}
__device__ __forceinline__ void mma16816(float* c, const uint32_t* a, const uint32_t* b) {
    asm volatile(
        "mma.sync.aligned.m16n8k16.row.col.f32.f16.f16.f32 "
        "{%0,%1,%2,%3}, {%4,%5,%6,%7}, {%8,%9}, {%0,%1,%2,%3};"
        : "+f"(c[0]), "+f"(c[1]), "+f"(c[2]), "+f"(c[3])
        : "r"(a[0]), "r"(a[1]), "r"(a[2]), "r"(a[3]), "r"(b[0]), "r"(b[1]));
}

// ======= shared GEMM core: 128x128x64 tile, 3-stage, single-buffered frags =======
// Latency hiding comes from 2 CTAs/SM (4 warps/SMSP), not register pipelining.
struct GemmCore {
    const __half* pA;
    const __half* pB;
    int ldaStep, ldbStep;      // 32*ld
    uint32_t sA0, sB0;
    uint32_t aOff, bOff;

    __device__ __forceinline__ void init(const __half* AB, const __half* BB,
                                         int lda, int ldb, int rowBase, int colBase,
                                         int tid, int lane, int wm, int wn)
    {
        const int tr = tid >> 3;       // 0..31
        const int tc = tid & 7;        // 16B chunk in 128B row
        pA = AB + (long)(rowBase + tr) * lda + tc * 8;
        pB = BB + (long)(colBase + tr) * ldb + tc * 8;
        ldaStep = 32 * lda;
        ldbStep = 32 * ldb;
        sA0 = tr * ROWB + tc * 16;
        sB0 = TILE_A + tr * ROWB + tc * 16;

        const int j = lane >> 3, r = lane & 7;
        aOff = (uint32_t)(wm * 64 + (j & 1) * 8 + r) * ROWB + ((j >> 1) * 8) * 2;
        bOff = (uint32_t)(wn * 32 + (j >> 1) * 8 + r) * ROWB + ((j & 1) * 8) * 2;
    }

    __device__ __forceinline__ void load_stage(uint32_t sbase, int k0)
    {
#pragma unroll
        for (int i = 0; i < 4; i++)
            cp_async16(sbase + sA0 + i * (32 * ROWB), pA + k0 + i * ldaStep);
#pragma unroll
        for (int i = 0; i < 4; i++)
            cp_async16(sbase + sB0 + i * (32 * ROWB), pB + k0 + i * ldbStep);
    }

    __device__ __forceinline__ void run(uint32_t sb, int kTiles, float acc[4][4][4])
    {
#pragma unroll
        for (int s = 0; s < 2; s++) {
            load_stage(sb + s * WSTAGE, s * BK);
            cp_commit();
        }

        uint32_t ah[4][4], bh[4][2];

        for (int kt = 0; kt < kTiles; kt++) {
            cp_wait<1>();
            __syncthreads();

            {
                int ft = kt + 2;
                if (ft < kTiles)
                    load_stage(sb + (ft % 3) * WSTAGE, ft * BK);
                cp_commit();
            }

            const uint32_t stage = sb + (kt % 3) * WSTAGE;

#pragma unroll
            for (int ks = 0; ks < 4; ks++) {
                const uint32_t kb = ks * 32;
#pragma unroll
                for (int mt = 0; mt < 4; mt++)
                    ldsm4(ah[mt], stage + aOff + mt * 16 * ROWB + kb);
#pragma unroll
                for (int p = 0; p < 2; p++) {
                    uint32_t t[4];
                    ldsm4(t, stage + TILE_A + bOff + p * 16 * ROWB + kb);
                    bh[2 * p][0] = t[0]; bh[2 * p][1] = t[1];
                    bh[2 * p + 1][0] = t[2]; bh[2 * p + 1][1] = t[3];
                }
#pragma unroll
                for (int mt = 0; mt < 4; mt++)
#pragma unroll
                    for (int nt = 0; nt < 4; nt++)
                        mma16816(acc[mt][nt], ah[mt], bh[nt]);
            }
        }
    }
};

// ============ fused projections: Q, K, Vt in ONE launch (2304 CTAs) ============
__global__ void __launch_bounds__(256, 2) proj_fused()
{
    extern __shared__ char smem[];
    const uint32_t sb = smem_u32(smem);
    const int tid  = threadIdx.x;
    const int lane = tid & 31;
    const int wid  = tid >> 5;
    const int wm   = wid & 1;
    const int wn   = wid >> 1;

    const int bx = blockIdx.x;
    const int op  = bx / 768;          // 0:Q 1:K 2:Vt
    const int rem = bx % 768;

    const __half* AB;
    const __half* BB;
    __half* Ch;
    int lda, ldb, ldc, rowBase, colBase;

    if (op < 2) {
        int nx = rem % 6, my = rem / 6;        // DIM/128=6 n-tiles, MTOT/128=128 m-tiles
        AB = g_xh; BB = (op == 0) ? g_Wqh : g_Wkh;
        Ch = (op == 0) ? g_Qh : g_Kh;
        lda = DIM; ldb = DIM; ldc = DIM;
        rowBase = my * BM; colBase = nx * BN;
    } else {
        int nx = rem % 128, my = rem / 128;    // MTOT/128=128 n-tiles, DIM/128=6 m-tiles
        AB = g_Wvh; BB = g_xh; Ch = g_Vth;
        lda = DIM; ldb = DIM; ldc = MTOT;
        rowBase = my * BM; colBase = nx * BN;
    }

    float acc[4][4][4];
#pragma unroll
    for (int a = 0; a < 4; a++)
#pragma unroll
        for (int b = 0; b < 4; b++)
#pragma unroll
            for (int q = 0; q < 4; q++) acc[a][b][q] = 0.f;

    GemmCore core;
    core.init(AB, BB, lda, ldb, rowBase, colBase, tid, lane, wm, wn);
    core.run(sb, DIM / BK, acc);

    const int mRow0 = rowBase + wm * 64 + (lane >> 2);
    const int nCol0 = colBase + wn * 32 + 2 * (lane & 3);
#pragma unroll
    for (int mt = 0; mt < 4; mt++) {
#pragma unroll
        for (int nt = 0; nt < 4; nt++) {
            float* c = acc[mt][nt];
            long r0 = mRow0 + mt * 16;
            int  cc = nCol0 + nt * 8;
#pragma unroll
            for (int h = 0; h < 2; h++) {
                __half2 hp;
                hp.x = __float2half(c[2 * h]);
                hp.y = __float2half(c[2 * h + 1]);
                *(__half2*)(Ch + (r0 + 8 * h) * (long)ldc + cc) = hp;
            }
        }
    }
}

// ============ scores GEMM: Ph = exp(scale * Qh@Kh^T), accumulate row sums ============
__global__ void __launch_bounds__(256, 2) gemm_scores(float scale)
{
    extern __shared__ char smem[];
    const uint32_t sb = smem_u32(smem);
    const int tid  = threadIdx.x;
    const int lane = tid & 31;
    const int wid  = tid >> 5;
    const int wm   = wid & 1;
    const int wn   = wid >> 1;
    const long z = blockIdx.z;

    const __half* AB = g_Qh + z * (long)SEQ * DIM;
    const __half* BB = g_Kh + z * (long)SEQ * DIM;

    const int rowBase = blockIdx.y * BM;
    const int colBase = blockIdx.x * BN;

    float acc[4][4][4];
#pragma unroll
    for (int a = 0; a < 4; a++)
#pragma unroll
        for (int b = 0; b < 4; b++)
#pragma unroll
            for (int q = 0; q < 4; q++) acc[a][b][q] = 0.f;

    GemmCore core;
    core.init(AB, BB, DIM, DIM, rowBase, colBase, tid, lane, wm, wn);
    core.run(sb, DIM / BK, acc);

    __half* Ch = g_Ph + z * (long)SEQ * SEQ;
    const int mRow0 = rowBase + wm * 64 + (lane >> 2);
    const int nCol0 = colBase + wn * 32 + 2 * (lane & 3);

    float rsum[4][2];
#pragma unroll
    for (int mt = 0; mt < 4; mt++) { rsum[mt][0] = 0.f; rsum[mt][1] = 0.f; }

#pragma unroll
    for (int mt = 0; mt < 4; mt++) {
#pragma unroll
        for (int nt = 0; nt < 4; nt++) {
            float* c = acc[mt][nt];
            long r0 = mRow0 + mt * 16;
            int  cc = nCol0 + nt * 8;
#pragma unroll
            for (int h = 0; h < 2; h++) {
                float e0 = __expf(c[2 * h]     * scale);
                float e1 = __expf(c[2 * h + 1] * scale);
                rsum[mt][h] += e0 + e1;
                __half2 hp = __floats2half2_rn(e0, e1);
                *(__half2*)(Ch + (r0 + 8 * h) * (long)SEQ + cc) = hp;
            }
        }
    }

#pragma unroll
    for (int mt = 0; mt < 4; mt++) {
#pragma unroll
        for (int h = 0; h < 2; h++) {
            float p = rsum[mt][h];
            p += __shfl_xor_sync(0xffffffffu, p, 1);
            p += __shfl_xor_sync(0xffffffffu, p, 2);
            if ((lane & 3) == 0) {
                long row = z * SEQ + mRow0 + mt * 16 + 8 * h;
                atomicAdd(&g_rowsum[row], p);
            }
        }
    }
}

// ============ AV GEMM: out = (Ph @ Vth^T) / rowsum ============
__global__ void __launch_bounds__(256, 2) gemm_av(float* __restrict__ out)
{
    extern __shared__ char smem[];
    const uint32_t sb = smem_u32(smem);
    const int tid  = threadIdx.x;
    const int lane = tid & 31;
    const int wid  = tid >> 5;
    const int wm   = wid & 1;
    const int wn   = wid >> 1;
    const long z = blockIdx.z;

    const __half* AB = g_Ph  + z * (long)SEQ * SEQ;
    const __half* BB = g_Vth + z * (long)SEQ;

    const int rowBase = blockIdx.y * BM;
    const int colBase = blockIdx.x * BN;

    float acc[4][4][4];
#pragma unroll
    for (int a = 0; a < 4; a++)
#pragma unroll
        for (int b = 0; b < 4; b++)
#pragma unroll
            for (int q = 0; q < 4; q++) acc[a][b][q] = 0.f;

    GemmCore core;
    core.init(AB, BB, SEQ, MTOT, rowBase, colBase, tid, lane, wm, wn);
    core.run(sb, SEQ / BK, acc);

    float* Cff = out + z * (long)SEQ * DIM;
    const int mRow0 = rowBase + wm * 64 + (lane >> 2);
    const int nCol0 = colBase + wn * 32 + 2 * (lane & 3);

    float inv[4][2];
#pragma unroll
    for (int mt = 0; mt < 4; mt++)
#pragma unroll
        for (int h = 0; h < 2; h++)
            inv[mt][h] = 1.0f / g_rowsum[z * SEQ + mRow0 + mt * 16 + 8 * h];

#pragma unroll
    for (int mt = 0; mt < 4; mt++) {
#pragma unroll
        for (int nt = 0; nt < 4; nt++) {
            float* c = acc[mt][nt];
            long r0 = mRow0 + mt * 16;
            int  cc = nCol0 + nt * 8;
            *(float2*)(Cff + r0 * (long)DIM + cc) =
                make_float2(c[0] * inv[mt][0], c[1] * inv[mt][0]);
            *(float2*)(Cff + (r0 + 8) * (long)DIM + cc) =
                make_float2(c[2] * inv[mt][1], c[3] * inv[mt][1]);
        }
    }
}

// ---------------- fused conversions + rowsum zeroing ----------------
#define N4_X (MTOT*DIM/4)
#define N4_W (DIM*DIM/4)
#define N4_S (MTOT/4)
__global__ void __launch_bounds__(256) conv_fused(
    const float4* __restrict__ x, const float4* __restrict__ Wq,
    const float4* __restrict__ Wk, const float4* __restrict__ Wv)
{
    int i = blockIdx.x * 256 + threadIdx.x;
    const float4* s;
    __half2* d;
    int off;
    if (i < N4_X)                { s = x;  d = (__half2*)g_xh;  off = i; }
    else if (i < N4_X + N4_W)    { s = Wq; d = (__half2*)g_Wqh; off = i - N4_X; }
    else if (i < N4_X + 2*N4_W)  { s = Wk; d = (__half2*)g_Wkh; off = i - N4_X - N4_W; }
    else if (i < N4_X + 3*N4_W)  { s = Wv; d = (__half2*)g_Wvh; off = i - N4_X - 2*N4_W; }
    else if (i < N4_X + 3*N4_W + N4_S) {
        int o = i - N4_X - 3*N4_W;
        ((float4*)g_rowsum)[o] = make_float4(0.f, 0.f, 0.f, 0.f);
        return;
    }
    else return;
    float4 v = s[off];
    d[2 * off]     = __floats2half2_rn(v.x, v.y);
    d[2 * off + 1] = __floats2half2_rn(v.z, v.w);
}

// ---------------- host launcher ----------------
extern "C" void kernel_launch(void* const* d_in, const int* in_sizes, int n_in,
                              void* d_out, int out_size)
{
    const float* x  = (const float*)d_in[0];
    const float* Wq = (const float*)d_in[1];
    const float* Wk = (const float*)d_in[2];
    const float* Wv = (const float*)d_in[3];
    float* out = (float*)d_out;

    cudaFuncSetAttribute((const void*)proj_fused,  cudaFuncAttributeMaxDynamicSharedMemorySize, SMEM_G);
    cudaFuncSetAttribute((const void*)gemm_scores, cudaFuncAttributeMaxDynamicSharedMemorySize, SMEM_G);
    cudaFuncSetAttribute((const void*)gemm_av,     cudaFuncAttributeMaxDynamicSharedMemorySize, SMEM_G);

    const float scale = 1.0f / sqrtf((float)DIM);

    // 1) conversions + rowsum zero, one launch
    {
        int total = N4_X + 3 * N4_W + N4_S;
        conv_fused<<<(total + 255) / 256, 256>>>((const float4*)x, (const float4*)Wq,
                                                 (const float4*)Wk, (const float4*)Wv);
    }

    // 2) Q-proj + K-proj + Vt in one 2304-CTA launch
    proj_fused<<<2304, 256, SMEM_G>>>();

    // 3) scores -> exp(s) fp16 + row sums
    {
        dim3 g(SEQ / BN, SEQ / BM, BATCH);
        gemm_scores<<<g, 256, SMEM_G>>>(scale);
    }

    // 4) H = (Ph @ Vth^T) / rowsum -> fp32 out
    {
        dim3 g(DIM / BN, SEQ / BM, BATCH);
        gemm_av<<<g, 256, SMEM_G>>>(out);
    }
}

// round 15
// speedup vs baseline: 2.6259x; 1.0541x over previous
#include <cuda_runtime.h>
#include <cuda_fp16.h>
#include <math.h>
#include <stdint.h>

#define BATCH 8
#define SEQ   2048
#define DIM   768
#define MTOT  (BATCH*SEQ)

// ---------------- static device scratch ----------------
__device__ __half g_xh [(size_t)MTOT*DIM];
__device__ __half g_WqT[DIM*DIM];                  // Wq transposed: [in, out]
__device__ __half g_WkT[DIM*DIM];                  // Wk transposed
__device__ __half g_Wvh[DIM*DIM];
__device__ __half g_NT [DIM*DIM];                  // N^T where N = Wq^T Wk (scores = x N x^T)
__device__ __half g_G  [(size_t)MTOT*DIM];         // G = x @ N
__device__ __half g_Vth[(size_t)DIM*MTOT];
__device__ __half g_Ph [(size_t)BATCH*SEQ*SEQ];    // exp(s) unnormalized
__device__ float  g_rowsum[MTOT];

// ---------------- tiling: 128x128x64, 3-stage, 2 CTAs/SM ----------------
#define BM 128
#define BN 128
#define BK 64
#define ROWB 144
#define TILE_A (128*ROWB)
#define TILE_B (128*ROWB)
#define WSTAGE (TILE_A + TILE_B)
#define SMEM_G (3*WSTAGE)              // 110592 B -> 2 CTAs/SM

// ---------------- PTX helpers ----------------
__device__ __forceinline__ uint32_t smem_u32(const void* p) {
    uint32_t a;
    asm("{ .reg .u64 t; cvta.to.shared.u64 t, %1; cvt.u32.u64 %0, t; }" : "=r"(a) : "l"(p));
    return a;
}
__device__ __forceinline__ void cp_async16(uint32_t saddr, const void* gaddr) {
    asm volatile("cp.async.cg.shared.global [%0], [%1], 16;" :: "r"(saddr), "l"(gaddr));
}
__device__ __forceinline__ void cp_commit() {
    asm volatile("cp.async.commit_group;" ::: "memory");
}
template<int N> __device__ __forceinline__ void cp_wait() {
    asm volatile("cp.async.wait_group %0;" :: "n"(N) : "memory");
}
__device__ __forceinline__ void ldsm4(uint32_t* r, uint32_t addr) {
    asm volatile("ldmatrix.sync.aligned.m8n8.x4.shared.b16 {%0,%1,%2,%3}, [%4];"
                 : "=r"(r[0]), "=r"(r[1]), "=r"(r[2]), "=r"(r[3]) : "r"(addr));
}
__device__ __forceinline__ void mma16816(float* c, const uint32_t* a, const uint32_t* b) {
    asm volatile(
        "mma.sync.aligned.m16n8k16.row.col.f32.f16.f16.f32 "
        "{%0,%1,%2,%3}, {%4,%5,%6,%7}, {%8,%9}, {%0,%1,%2,%3};"
        : "+f"(c[0]), "+f"(c[1]), "+f"(c[2]), "+f"(c[3])
        : "r"(a[0]), "r"(a[1]), "r"(a[2]), "r"(a[3]), "r"(b[0]), "r"(b[1]));
}

// ======= shared GEMM core: 128x128x64 tile, 3-stage, single-buffered frags =======
struct GemmCore {
    const __half* pA;
    const __half* pB;
    int ldaStep, ldbStep;
    uint32_t sA0, sB0;
    uint32_t aOff, bOff;

    __device__ __forceinline__ void init(const __half* AB, const __half* BB,
                                         int lda, int ldb, int rowBase, int colBase,
                                         int tid, int lane, int wm, int wn)
    {
        const int tr = tid >> 3;
        const int tc = tid & 7;
        pA = AB + (long)(rowBase + tr) * lda + tc * 8;
        pB = BB + (long)(colBase + tr) * ldb + tc * 8;
        ldaStep = 32 * lda;
        ldbStep = 32 * ldb;
        sA0 = tr * ROWB + tc * 16;
        sB0 = TILE_A + tr * ROWB + tc * 16;

        const int j = lane >> 3, r = lane & 7;
        aOff = (uint32_t)(wm * 64 + (j & 1) * 8 + r) * ROWB + ((j >> 1) * 8) * 2;
        bOff = (uint32_t)(wn * 32 + (j >> 1) * 8 + r) * ROWB + ((j & 1) * 8) * 2;
    }

    __device__ __forceinline__ void load_stage(uint32_t sbase, int k0)
    {
#pragma unroll
        for (int i = 0; i < 4; i++)
            cp_async16(sbase + sA0 + i * (32 * ROWB), pA + k0 + i * ldaStep);
#pragma unroll
        for (int i = 0; i < 4; i++)
            cp_async16(sbase + sB0 + i * (32 * ROWB), pB + k0 + i * ldbStep);
    }

    __device__ __forceinline__ void run(uint32_t sb, int kTiles, float acc[4][4][4])
    {
#pragma unroll
        for (int s = 0; s < 2; s++) {
            load_stage(sb + s * WSTAGE, s * BK);
            cp_commit();
        }

        uint32_t ah[4][4], bh[4][2];

        for (int kt = 0; kt < kTiles; kt++) {
            cp_wait<1>();
            __syncthreads();

            {
                int ft = kt + 2;
                if (ft < kTiles)
                    load_stage(sb + (ft % 3) * WSTAGE, ft * BK);
                cp_commit();
            }

            const uint32_t stage = sb + (kt % 3) * WSTAGE;

#pragma unroll
            for (int ks = 0; ks < 4; ks++) {
                const uint32_t kb = ks * 32;
#pragma unroll
                for (int mt = 0; mt < 4; mt++)
                    ldsm4(ah[mt], stage + aOff + mt * 16 * ROWB + kb);
#pragma unroll
                for (int p = 0; p < 2; p++) {
                    uint32_t t[4];
                    ldsm4(t, stage + TILE_A + bOff + p * 16 * ROWB + kb);
                    bh[2 * p][0] = t[0]; bh[2 * p][1] = t[1];
                    bh[2 * p + 1][0] = t[2]; bh[2 * p + 1][1] = t[3];
                }
#pragma unroll
                for (int mt = 0; mt < 4; mt++)
#pragma unroll
                    for (int nt = 0; nt < 4; nt++)
                        mma16816(acc[mt][nt], ah[mt], bh[nt]);
            }
        }
    }
};

// ---- shared fp16 epilogue: write acc (optionally scaled) to Ch[row*ldc+col] ----
__device__ __forceinline__ void epilogue_h(float acc[4][4][4], __half* Ch, long ldc,
                                           int mRow0, int nCol0)
{
#pragma unroll
    for (int mt = 0; mt < 4; mt++) {
#pragma unroll
        for (int nt = 0; nt < 4; nt++) {
            float* c = acc[mt][nt];
            long r0 = mRow0 + mt * 16;
            int  cc = nCol0 + nt * 8;
#pragma unroll
            for (int h = 0; h < 2; h++) {
                __half2 hp;
                hp.x = __float2half(c[2 * h]);
                hp.y = __float2half(c[2 * h + 1]);
                *(__half2*)(Ch + (r0 + 8 * h) * ldc + cc) = hp;
            }
        }
    }
}

// ============ N^T = NT(WkT, WqT): 36 CTAs, 768x768 out ============
// NT[j,i] = sum_o Wk[o,j]*Wq[o,i]; scores = x N x^T with N[i,j].
__global__ void __launch_bounds__(256, 2) gemm_n()
{
    extern __shared__ char smem[];
    const uint32_t sb = smem_u32(smem);
    const int tid  = threadIdx.x;
    const int lane = tid & 31;
    const int wid  = tid >> 5;
    const int wm   = wid & 1;
    const int wn   = wid >> 1;

    const int rowBase = blockIdx.y * BM;   // j
    const int colBase = blockIdx.x * BN;   // i

    float acc[4][4][4];
#pragma unroll
    for (int a = 0; a < 4; a++)
#pragma unroll
        for (int b = 0; b < 4; b++)
#pragma unroll
            for (int q = 0; q < 4; q++) acc[a][b][q] = 0.f;

    GemmCore core;
    core.init(g_WkT, g_WqT, DIM, DIM, rowBase, colBase, tid, lane, wm, wn);
    core.run(sb, DIM / BK, acc);

    const int mRow0 = rowBase + wm * 64 + (lane >> 2);
    const int nCol0 = colBase + wn * 32 + 2 * (lane & 3);
    epilogue_h(acc, g_NT, DIM, mRow0, nCol0);
}

// ============ fused: G = NT(xh, NT) and Vt = NT(Wvh, xh) in ONE launch (1536 CTAs) ============
__global__ void __launch_bounds__(256, 2) proj_fused()
{
    extern __shared__ char smem[];
    const uint32_t sb = smem_u32(smem);
    const int tid  = threadIdx.x;
    const int lane = tid & 31;
    const int wid  = tid >> 5;
    const int wm   = wid & 1;
    const int wn   = wid >> 1;

    const int bx = blockIdx.x;
    const int op  = bx / 768;          // 0:G 1:Vt
    const int rem = bx % 768;

    const __half* AB;
    const __half* BB;
    __half* Ch;
    int lda, ldb, ldc, rowBase, colBase;

    if (op == 0) {
        // G[MTOT, DIM] = xh @ NT^T ; 6 n-tiles, 128 m-tiles
        int nx = rem % 6, my = rem / 6;
        AB = g_xh; BB = g_NT; Ch = g_G;
        lda = DIM; ldb = DIM; ldc = DIM;
        rowBase = my * BM; colBase = nx * BN;
    } else {
        // Vt[DIM, MTOT] = Wvh @ xh^T ; 128 n-tiles, 6 m-tiles
        int nx = rem % 128, my = rem / 128;
        AB = g_Wvh; BB = g_xh; Ch = g_Vth;
        lda = DIM; ldb = DIM; ldc = MTOT;
        rowBase = my * BM; colBase = nx * BN;
    }

    float acc[4][4][4];
#pragma unroll
    for (int a = 0; a < 4; a++)
#pragma unroll
        for (int b = 0; b < 4; b++)
#pragma unroll
            for (int q = 0; q < 4; q++) acc[a][b][q] = 0.f;

    GemmCore core;
    core.init(AB, BB, lda, ldb, rowBase, colBase, tid, lane, wm, wn);
    core.run(sb, DIM / BK, acc);

    const int mRow0 = rowBase + wm * 64 + (lane >> 2);
    const int nCol0 = colBase + wn * 32 + 2 * (lane & 3);
    epilogue_h(acc, Ch, (long)ldc, mRow0, nCol0);
}

// ============ scores GEMM: Ph = exp(scale * G@x^T), accumulate row sums ============
__global__ void __launch_bounds__(256, 2) gemm_scores(float scale)
{
    extern __shared__ char smem[];
    const uint32_t sb = smem_u32(smem);
    const int tid  = threadIdx.x;
    const int lane = tid & 31;
    const int wid  = tid >> 5;
    const int wm   = wid & 1;
    const int wn   = wid >> 1;
    const long z = blockIdx.z;

    const __half* AB = g_G  + z * (long)SEQ * DIM;
    const __half* BB = g_xh + z * (long)SEQ * DIM;

    const int rowBase = blockIdx.y * BM;
    const int colBase = blockIdx.x * BN;

    float acc[4][4][4];
#pragma unroll
    for (int a = 0; a < 4; a++)
#pragma unroll
        for (int b = 0; b < 4; b++)
#pragma unroll
            for (int q = 0; q < 4; q++) acc[a][b][q] = 0.f;

    GemmCore core;
    core.init(AB, BB, DIM, DIM, rowBase, colBase, tid, lane, wm, wn);
    core.run(sb, DIM / BK, acc);

    __half* Ch = g_Ph + z * (long)SEQ * SEQ;
    const int mRow0 = rowBase + wm * 64 + (lane >> 2);
    const int nCol0 = colBase + wn * 32 + 2 * (lane & 3);

    float rsum[4][2];
#pragma unroll
    for (int mt = 0; mt < 4; mt++) { rsum[mt][0] = 0.f; rsum[mt][1] = 0.f; }

#pragma unroll
    for (int mt = 0; mt < 4; mt++) {
#pragma unroll
        for (int nt = 0; nt < 4; nt++) {
            float* c = acc[mt][nt];
            long r0 = mRow0 + mt * 16;
            int  cc = nCol0 + nt * 8;
#pragma unroll
            for (int h = 0; h < 2; h++) {
                float e0 = __expf(c[2 * h]     * scale);
                float e1 = __expf(c[2 * h + 1] * scale);
                rsum[mt][h] += e0 + e1;
                __half2 hp = __floats2half2_rn(e0, e1);
                *(__half2*)(Ch + (r0 + 8 * h) * (long)SEQ + cc) = hp;
            }
        }
    }

#pragma unroll
    for (int mt = 0; mt < 4; mt++) {
#pragma unroll
        for (int h = 0; h < 2; h++) {
            float p = rsum[mt][h];
            p += __shfl_xor_sync(0xffffffffu, p, 1);
            p += __shfl_xor_sync(0xffffffffu, p, 2);
            if ((lane & 3) == 0) {
                long row = z * SEQ + mRow0 + mt * 16 + 8 * h;
                atomicAdd(&g_rowsum[row], p);
            }
        }
    }
}

// ============ AV GEMM: out = (Ph @ Vth^T) / rowsum ============
__global__ void __launch_bounds__(256, 2) gemm_av(float* __restrict__ out)
{
    extern __shared__ char smem[];
    const uint32_t sb = smem_u32(smem);
    const int tid  = threadIdx.x;
    const int lane = tid & 31;
    const int wid  = tid >> 5;
    const int wm   = wid & 1;
    const int wn   = wid >> 1;
    const long z = blockIdx.z;

    const __half* AB = g_Ph  + z * (long)SEQ * SEQ;
    const __half* BB = g_Vth + z * (long)SEQ;

    const int rowBase = blockIdx.y * BM;
    const int colBase = blockIdx.x * BN;

    float acc[4][4][4];
#pragma unroll
    for (int a = 0; a < 4; a++)
#pragma unroll
        for (int b = 0; b < 4; b++)
#pragma unroll
            for (int q = 0; q < 4; q++) acc[a][b][q] = 0.f;

    GemmCore core;
    core.init(AB, BB, SEQ, MTOT, rowBase, colBase, tid, lane, wm, wn);
    core.run(sb, SEQ / BK, acc);

    float* Cff = out + z * (long)SEQ * DIM;
    const int mRow0 = rowBase + wm * 64 + (lane >> 2);
    const int nCol0 = colBase + wn * 32 + 2 * (lane & 3);

    float inv[4][2];
#pragma unroll
    for (int mt = 0; mt < 4; mt++)
#pragma unroll
        for (int h = 0; h < 2; h++)
            inv[mt][h] = 1.0f / g_rowsum[z * SEQ + mRow0 + mt * 16 + 8 * h];

#pragma unroll
    for (int mt = 0; mt < 4; mt++) {
#pragma unroll
        for (int nt = 0; nt < 4; nt++) {
            float* c = acc[mt][nt];
            long r0 = mRow0 + mt * 16;
            int  cc = nCol0 + nt * 8;
            *(float2*)(Cff + r0 * (long)DIM + cc) =
                make_float2(c[0] * inv[mt][0], c[1] * inv[mt][0]);
            *(float2*)(Cff + (r0 + 8) * (long)DIM + cc) =
                make_float2(c[2] * inv[mt][1], c[3] * inv[mt][1]);
        }
    }
}

// ---------------- fused conversions (+ Wq/Wk transpose) + rowsum zeroing ----------------
#define N4_X (MTOT*DIM/4)
#define N4_W (DIM*DIM/4)
#define N4_S (MTOT/4)
__global__ void __launch_bounds__(256) conv_fused(
    const float4* __restrict__ x, const float4* __restrict__ Wq,
    const float4* __restrict__ Wk, const float4* __restrict__ Wv)
{
    int i = blockIdx.x * 256 + threadIdx.x;
    if (i < N4_X) {
        float4 v = x[i];
        __half2* d = (__half2*)g_xh;
        d[2 * i]     = __floats2half2_rn(v.x, v.y);
        d[2 * i + 1] = __floats2half2_rn(v.z, v.w);
    } else if (i < N4_X + 2 * N4_W) {
        // Wq / Wk: write TRANSPOSED (WT[col*DIM + row])
        int t   = i - N4_X;
        int wsel = t / N4_W;           // 0:Wq 1:Wk
        int off  = t % N4_W;
        const float4* s = wsel ? Wk : Wq;
        __half* d = wsel ? g_WkT : g_WqT;
        float4 v = s[off];
        int row = off / (DIM / 4);
        int c0  = (off % (DIM / 4)) * 4;
        d[(c0 + 0) * DIM + row] = __float2half(v.x);
        d[(c0 + 1) * DIM + row] = __float2half(v.y);
        d[(c0 + 2) * DIM + row] = __float2half(v.z);
        d[(c0 + 3) * DIM + row] = __float2half(v.w);
    } else if (i < N4_X + 3 * N4_W) {
        int off = i - N4_X - 2 * N4_W;
        float4 v = Wv[off];
        __half2* d = (__half2*)g_Wvh;
        d[2 * off]     = __floats2half2_rn(v.x, v.y);
        d[2 * off + 1] = __floats2half2_rn(v.z, v.w);
    } else if (i < N4_X + 3 * N4_W + N4_S) {
        int o = i - N4_X - 3 * N4_W;
        ((float4*)g_rowsum)[o] = make_float4(0.f, 0.f, 0.f, 0.f);
    }
}

// ---------------- host launcher ----------------
extern "C" void kernel_launch(void* const* d_in, const int* in_sizes, int n_in,
                              void* d_out, int out_size)
{
    const float* x  = (const float*)d_in[0];
    const float* Wq = (const float*)d_in[1];
    const float* Wk = (const float*)d_in[2];
    const float* Wv = (const float*)d_in[3];
    float* out = (float*)d_out;

    cudaFuncSetAttribute((const void*)gemm_n,      cudaFuncAttributeMaxDynamicSharedMemorySize, SMEM_G);
    cudaFuncSetAttribute((const void*)proj_fused,  cudaFuncAttributeMaxDynamicSharedMemorySize, SMEM_G);
    cudaFuncSetAttribute((const void*)gemm_scores, cudaFuncAttributeMaxDynamicSharedMemorySize, SMEM_G);
    cudaFuncSetAttribute((const void*)gemm_av,     cudaFuncAttributeMaxDynamicSharedMemorySize, SMEM_G);

    const float scale = 1.0f / sqrtf((float)DIM);

    // 1) conversions (+ Wq/Wk transpose) + rowsum zero
    {
        int total = N4_X + 3 * N4_W + N4_S;
        conv_fused<<<(total + 255) / 256, 256>>>((const float4*)x, (const float4*)Wq,
                                                 (const float4*)Wk, (const float4*)Wv);
    }

    // 2) N^T = NT(WkT, WqT)  (36 CTAs)
    {
        dim3 g(DIM / BN, DIM / BM, 1);
        gemm_n<<<g, 256, SMEM_G>>>();
    }

    // 3) G = x@N and Vt = Wv@x^T in one 1536-CTA launch
    proj_fused<<<1536, 256, SMEM_G>>>();

    // 4) scores -> exp(s) fp16 + row sums
    {
        dim3 g(SEQ / BN, SEQ / BM, BATCH);
        gemm_scores<<<g, 256, SMEM_G>>>(scale);
    }

    // 5) H = (Ph @ Vth^T) / rowsum -> fp32 out
    {
        dim3 g(DIM / BN, SEQ / BM, BATCH);
        gemm_av<<<g, 256, SMEM_G>>>(out);
    }
}

// round 16
// speedup vs baseline: 2.7049x; 1.0301x over previous
#include <cuda_runtime.h>
#include <cuda_fp16.h>
#include <math.h>
#include <stdint.h>

#define BATCH 8
#define SEQ   2048
#define DIM   768
#define MTOT  (BATCH*SEQ)

// ---------------- static device scratch ----------------
__device__ __half g_xh [(size_t)MTOT*DIM];
__device__ __half g_WqT[DIM*DIM];
__device__ __half g_WkT[DIM*DIM];
__device__ __half g_Wvh[DIM*DIM];
__device__ __half g_NT [DIM*DIM];
__device__ __half g_G  [(size_t)MTOT*DIM];
__device__ __half g_Vth[(size_t)DIM*MTOT];
__device__ __half g_Ph [(size_t)BATCH*SEQ*SEQ];
__device__ float  g_rowsum[MTOT];

// ---- sync state: queue head + dependency counters (zeroed by conv_fused) ----
__device__ __align__(16) int g_sync[320];
#define SY_QHEAD 0
#define SY_NCNT  1
#define SY_VT    8      // [my*8 + z], 48 entries, target 16
#define SY_G     64     // [global row-block 0..127], target 6
#define SY_S     192    // [z*16 + qb], target 16

#define NT_N   36
#define NT_VT  768
#define NT_G   768
#define NT_S   2048
#define NT_AV  768
#define T0_VT  (NT_N)                       // 36
#define T0_G   (T0_VT + NT_VT)              // 804
#define T0_S   (T0_G + NT_G)                // 1572
#define T0_AV  (T0_S + NT_S)                // 3620
#define NTILES (T0_AV + NT_AV)              // 4388
#define GRID_P 296

// ---------------- tiling: 128x128x64, 3-stage, 2 CTAs/SM ----------------
#define BM 128
#define BN 128
#define BK 64
#define ROWB 144
#define TILE_A (128*ROWB)
#define TILE_B (128*ROWB)
#define WSTAGE (TILE_A + TILE_B)
#define SMEM_G (3*WSTAGE)              // 110592 B

// ---------------- PTX helpers ----------------
__device__ __forceinline__ uint32_t smem_u32(const void* p) {
    uint32_t a;
    asm("{ .reg .u64 t; cvta.to.shared.u64 t, %1; cvt.u32.u64 %0, t; }" : "=r"(a) : "l"(p));
    return a;
}
__device__ __forceinline__ void cp_async16(uint32_t saddr, const void* gaddr) {
    asm volatile("cp.async.cg.shared.global [%0], [%1], 16;" :: "r"(saddr), "l"(gaddr));
}
__device__ __forceinline__ void cp_commit() {
    asm volatile("cp.async.commit_group;" ::: "memory");
}
template<int N> __device__ __forceinline__ void cp_wait() {
    asm volatile("cp.async.wait_group %0;" :: "n"(N) : "memory");
}
__device__ __forceinline__ void ldsm4(uint32_t* r, uint32_t addr) {
    asm volatile("ldmatrix.sync.aligned.m8n8.x4.shared.b16 {%0,%1,%2,%3}, [%4];"
                 : "=r"(r[0]), "=r"(r[1]), "=r"(r[2]), "=r"(r[3]) : "r"(addr));
}
__device__ __forceinline__ void mma16816(float* c, const uint32_t* a, const uint32_t* b) {
    asm volatile(
        "mma.sync.aligned.m16n8k16.row.col.f32.f16.f16.f32 "
        "{%0,%1,%2,%3}, {%4,%5,%6,%7}, {%8,%9}, {%0,%1,%2,%3};"
        : "+f"(c[0]), "+f"(c[1]), "+f"(c[2]), "+f"(c[3])
        : "r"(a[0]), "r"(a[1]), "r"(a[2]), "r"(a[3]), "r"(b[0]), "r"(b[1]));
}

// ======= shared GEMM core: 128x128x64 tile, 3-stage, single-buffered frags =======
struct GemmCore {
    const __half* pA;
    const __half* pB;
    int ldaStep, ldbStep;
    uint32_t sA0, sB0;
    uint32_t aOff, bOff;

    __device__ __forceinline__ void init(const __half* AB, const __half* BB,
                                         int lda, int ldb, int rowBase, int colBase,
                                         int tid, int lane, int wm, int wn)
    {
        const int tr = tid >> 3;
        const int tc = tid & 7;
        pA = AB + (long)(rowBase + tr) * lda + tc * 8;
        pB = BB + (long)(colBase + tr) * ldb + tc * 8;
        ldaStep = 32 * lda;
        ldbStep = 32 * ldb;
        sA0 = tr * ROWB + tc * 16;
        sB0 = TILE_A + tr * ROWB + tc * 16;

        const int j = lane >> 3, r = lane & 7;
        aOff = (uint32_t)(wm * 64 + (j & 1) * 8 + r) * ROWB + ((j >> 1) * 8) * 2;
        bOff = (uint32_t)(wn * 32 + (j >> 1) * 8 + r) * ROWB + ((j & 1) * 8) * 2;
    }

    __device__ __forceinline__ void load_stage(uint32_t sbase, int k0)
    {
#pragma unroll
        for (int i = 0; i < 4; i++)
            cp_async16(sbase + sA0 + i * (32 * ROWB), pA + k0 + i * ldaStep);
#pragma unroll
        for (int i = 0; i < 4; i++)
            cp_async16(sbase + sB0 + i * (32 * ROWB), pB + k0 + i * ldbStep);
    }

    __device__ __forceinline__ void run(uint32_t sb, int kTiles, float acc[4][4][4])
    {
#pragma unroll
        for (int s = 0; s < 2; s++) {
            load_stage(sb + s * WSTAGE, s * BK);
            cp_commit();
        }

        uint32_t ah[4][4], bh[4][2];

        for (int kt = 0; kt < kTiles; kt++) {
            cp_wait<1>();
            __syncthreads();

            {
                int ft = kt + 2;
                if (ft < kTiles)
                    load_stage(sb + (ft % 3) * WSTAGE, ft * BK);
                cp_commit();
            }

            const uint32_t stage = sb + (kt % 3) * WSTAGE;

#pragma unroll
            for (int ks = 0; ks < 4; ks++) {
                const uint32_t kb = ks * 32;
#pragma unroll
                for (int mt = 0; mt < 4; mt++)
                    ldsm4(ah[mt], stage + aOff + mt * 16 * ROWB + kb);
#pragma unroll
                for (int p = 0; p < 2; p++) {
                    uint32_t t[4];
                    ldsm4(t, stage + TILE_A + bOff + p * 16 * ROWB + kb);
                    bh[2 * p][0] = t[0]; bh[2 * p][1] = t[1];
                    bh[2 * p + 1][0] = t[2]; bh[2 * p + 1][1] = t[3];
                }
#pragma unroll
                for (int mt = 0; mt < 4; mt++)
#pragma unroll
                    for (int nt = 0; nt < 4; nt++)
                        mma16816(acc[mt][nt], ah[mt], bh[nt]);
            }
        }
    }
};

__device__ __forceinline__ void acc_zero(float acc[4][4][4]) {
#pragma unroll
    for (int a = 0; a < 4; a++)
#pragma unroll
        for (int b = 0; b < 4; b++)
#pragma unroll
            for (int q = 0; q < 4; q++) acc[a][b][q] = 0.f;
}

__device__ __forceinline__ void epilogue_h(float acc[4][4][4], __half* Ch, long ldc,
                                           int mRow0, int nCol0)
{
#pragma unroll
    for (int mt = 0; mt < 4; mt++) {
#pragma unroll
        for (int nt = 0; nt < 4; nt++) {
            float* c = acc[mt][nt];
            long r0 = mRow0 + mt * 16;
            int  cc = nCol0 + nt * 8;
#pragma unroll
            for (int h = 0; h < 2; h++) {
                __half2 hp;
                hp.x = __float2half(c[2 * h]);
                hp.y = __float2half(c[2 * h + 1]);
                *(__half2*)(Ch + (r0 + 8 * h) * ldc + cc) = hp;
            }
        }
    }
}

// spin until *c >= target (tid0 spins, CTA joins at barrier)
__device__ __forceinline__ void dep_wait(int idx, int target, int tid) {
    if (tid == 0) {
        volatile int* c = &g_sync[idx];
        while (*c < target) __nanosleep(64);
    }
    __syncthreads();
}

// all threads: fence; then tid0 bumps counter
__device__ __forceinline__ void dep_signal(int idx, int tid) {
    __threadfence();
    __syncthreads();
    if (tid == 0) atomicAdd(&g_sync[idx], 1);
}

// ================= persistent mega-kernel: all 4 GEMM phases =================
__global__ void __launch_bounds__(256, 2) mega(float* __restrict__ out)
{
    extern __shared__ char smem[];
    const uint32_t sb = smem_u32(smem);
    const int tid  = threadIdx.x;
    const int lane = tid & 31;
    const int wid  = tid >> 5;
    const int wm   = wid & 1;
    const int wn   = wid >> 1;
    const float scale = rsqrtf((float)DIM);

    __shared__ int s_t;

    for (;;) {
        __syncthreads();                    // all warps done with prev tile & smem
        if (tid == 0) s_t = atomicAdd(&g_sync[SY_QHEAD], 1);
        __syncthreads();
        const int t = s_t;
        if (t >= NTILES) return;

        float acc[4][4][4];
        acc_zero(acc);
        GemmCore core;

        if (t < T0_VT) {
            // ---- N^T = NT(WkT, WqT) ----
            int bx = t % 6, by = t / 6;
            core.init(g_WkT, g_WqT, DIM, DIM, by * BM, bx * BN, tid, lane, wm, wn);
            core.run(sb, DIM / BK, acc);
            int mRow0 = by * BM + wm * 64 + (lane >> 2);
            int nCol0 = bx * BN + wn * 32 + 2 * (lane & 3);
            epilogue_h(acc, g_NT, DIM, mRow0, nCol0);
            dep_signal(SY_NCNT, tid);
        }
        else if (t < T0_G) {
            // ---- Vt = NT(Wvh, xh): [DIM, MTOT] ----
            int i2 = t - T0_VT;
            int nx = i2 % 128, my = i2 / 128;
            core.init(g_Wvh, g_xh, DIM, DIM, my * BM, nx * BN, tid, lane, wm, wn);
            core.run(sb, DIM / BK, acc);
            int mRow0 = my * BM + wm * 64 + (lane >> 2);
            int nCol0 = nx * BN + wn * 32 + 2 * (lane & 3);
            epilogue_h(acc, g_Vth, MTOT, mRow0, nCol0);
            dep_signal(SY_VT + my * 8 + (nx >> 4), tid);
        }
        else if (t < T0_S) {
            // ---- G = NT(xh, NT): [MTOT, DIM] ----
            int i3 = t - T0_G;
            int nx = i3 % 6, my = i3 / 6;
            dep_wait(SY_NCNT, NT_N, tid);
            core.init(g_xh, g_NT, DIM, DIM, my * BM, nx * BN, tid, lane, wm, wn);
            core.run(sb, DIM / BK, acc);
            int mRow0 = my * BM + wm * 64 + (lane >> 2);
            int nCol0 = nx * BN + wn * 32 + 2 * (lane & 3);
            epilogue_h(acc, g_G, DIM, mRow0, nCol0);
            dep_signal(SY_G + my, tid);
        }
        else if (t < T0_AV) {
            // ---- scores: Ph = exp(scale * G@x^T) + row sums ----
            int i4 = t - T0_S;
            int z = i4 >> 8, r = i4 & 255;
            int qb = r >> 4, kb = r & 15;
            dep_wait(SY_G + z * 16 + qb, 6, tid);

            const __half* AB = g_G  + (long)z * SEQ * DIM;
            const __half* BB = g_xh + (long)z * SEQ * DIM;
            core.init(AB, BB, DIM, DIM, qb * BM, kb * BN, tid, lane, wm, wn);
            core.run(sb, DIM / BK, acc);

            __half* Ch = g_Ph + (long)z * SEQ * SEQ;
            int mRow0 = qb * BM + wm * 64 + (lane >> 2);
            int nCol0 = kb * BN + wn * 32 + 2 * (lane & 3);

            float rsum[4][2];
#pragma unroll
            for (int mt = 0; mt < 4; mt++) { rsum[mt][0] = 0.f; rsum[mt][1] = 0.f; }

#pragma unroll
            for (int mt = 0; mt < 4; mt++) {
#pragma unroll
                for (int nt = 0; nt < 4; nt++) {
                    float* c = acc[mt][nt];
                    long r0 = mRow0 + mt * 16;
                    int  cc = nCol0 + nt * 8;
#pragma unroll
                    for (int h = 0; h < 2; h++) {
                        float e0 = __expf(c[2 * h]     * scale);
                        float e1 = __expf(c[2 * h + 1] * scale);
                        rsum[mt][h] += e0 + e1;
                        __half2 hp = __floats2half2_rn(e0, e1);
                        *(__half2*)(Ch + (r0 + 8 * h) * (long)SEQ + cc) = hp;
                    }
                }
            }
#pragma unroll
            for (int mt = 0; mt < 4; mt++) {
#pragma unroll
                for (int h = 0; h < 2; h++) {
                    float p = rsum[mt][h];
                    p += __shfl_xor_sync(0xffffffffu, p, 1);
                    p += __shfl_xor_sync(0xffffffffu, p, 2);
                    if ((lane & 3) == 0) {
                        long row = (long)z * SEQ + mRow0 + mt * 16 + 8 * h;
                        atomicAdd(&g_rowsum[row], p);
                    }
                }
            }
            dep_signal(SY_S + z * 16 + qb, tid);
        }
        else {
            // ---- av: out = (Ph @ Vt^T) / rowsum ----
            int i5 = t - T0_AV;
            int z = i5 / 96, r = i5 % 96;
            int qb = r / 6, nxc = r % 6;
            dep_wait(SY_S + z * 16 + qb, 16, tid);
            dep_wait(SY_VT + nxc * 8 + z, 16, tid);

            const __half* AB = g_Ph  + (long)z * SEQ * SEQ;
            const __half* BB = g_Vth + (long)z * SEQ;
            core.init(AB, BB, SEQ, MTOT, qb * BM, nxc * BN, tid, lane, wm, wn);
            core.run(sb, SEQ / BK, acc);

            float* Cff = out + (long)z * SEQ * DIM;
            int mRow0 = qb * BM + wm * 64 + (lane >> 2);
            int nCol0 = nxc * BN + wn * 32 + 2 * (lane & 3);

            float inv[4][2];
#pragma unroll
            for (int mt = 0; mt < 4; mt++)
#pragma unroll
                for (int h = 0; h < 2; h++)
                    inv[mt][h] = 1.0f / g_rowsum[(long)z * SEQ + mRow0 + mt * 16 + 8 * h];

#pragma unroll
            for (int mt = 0; mt < 4; mt++) {
#pragma unroll
                for (int nt = 0; nt < 4; nt++) {
                    float* c = acc[mt][nt];
                    long r0 = mRow0 + mt * 16;
                    int  cc = nCol0 + nt * 8;
                    *(float2*)(Cff + r0 * (long)DIM + cc) =
                        make_float2(c[0] * inv[mt][0], c[1] * inv[mt][0]);
                    *(float2*)(Cff + (r0 + 8) * (long)DIM + cc) =
                        make_float2(c[2] * inv[mt][1], c[3] * inv[mt][1]);
                }
            }
        }
    }
}

// ---------------- fused conversions + transpose + rowsum/sync zeroing ----------------
#define N4_X (MTOT*DIM/4)
#define N4_W (DIM*DIM/4)
#define N4_S (MTOT/4)
#define N4_Y 80                        // g_sync: 320 ints = 80 float4
__global__ void __launch_bounds__(256) conv_fused(
    const float4* __restrict__ x, const float4* __restrict__ Wq,
    const float4* __restrict__ Wk, const float4* __restrict__ Wv)
{
    int i = blockIdx.x * 256 + threadIdx.x;
    if (i < N4_X) {
        float4 v = x[i];
        __half2* d = (__half2*)g_xh;
        d[2 * i]     = __floats2half2_rn(v.x, v.y);
        d[2 * i + 1] = __floats2half2_rn(v.z, v.w);
    } else if (i < N4_X + 2 * N4_W) {
        int t    = i - N4_X;
        int wsel = t / N4_W;
        int off  = t % N4_W;
        const float4* s = wsel ? Wk : Wq;
        __half* d = wsel ? g_WkT : g_WqT;
        float4 v = s[off];
        int row = off / (DIM / 4);
        int c0  = (off % (DIM / 4)) * 4;
        d[(c0 + 0) * DIM + row] = __float2half(v.x);
        d[(c0 + 1) * DIM + row] = __float2half(v.y);
        d[(c0 + 2) * DIM + row] = __float2half(v.z);
        d[(c0 + 3) * DIM + row] = __float2half(v.w);
    } else if (i < N4_X + 3 * N4_W) {
        int off = i - N4_X - 2 * N4_W;
        float4 v = Wv[off];
        __half2* d = (__half2*)g_Wvh;
        d[2 * off]     = __floats2half2_rn(v.x, v.y);
        d[2 * off + 1] = __floats2half2_rn(v.z, v.w);
    } else if (i < N4_X + 3 * N4_W + N4_S) {
        int o = i - N4_X - 3 * N4_W;
        ((float4*)g_rowsum)[o] = make_float4(0.f, 0.f, 0.f, 0.f);
    } else if (i < N4_X + 3 * N4_W + N4_S + N4_Y) {
        int o = i - N4_X - 3 * N4_W - N4_S;
        ((float4*)g_sync)[o] = make_float4(0.f, 0.f, 0.f, 0.f);
    }
}

// ---------------- host launcher ----------------
extern "C" void kernel_launch(void* const* d_in, const int* in_sizes, int n_in,
                              void* d_out, int out_size)
{
    const float* x  = (const float*)d_in[0];
    const float* Wq = (const float*)d_in[1];
    const float* Wk = (const float*)d_in[2];
    const float* Wv = (const float*)d_in[3];
    float* out = (float*)d_out;

    cudaFuncSetAttribute((const void*)mega, cudaFuncAttributeMaxDynamicSharedMemorySize, SMEM_G);

    // 1) conversions + transpose + counter zeroing
    {
        int total = N4_X + 3 * N4_W + N4_S + N4_Y;
        conv_fused<<<(total + 255) / 256, 256>>>((const float4*)x, (const float4*)Wq,
                                                 (const float4*)Wk, (const float4*)Wv);
    }

    // 2) everything else: one persistent launch
    mega<<<GRID_P, 256, SMEM_G>>>(out);
}